// round 1
// baseline (speedup 1.0000x reference)
#include <cuda_runtime.h>
#include <cuda_bf16.h>
#include <math.h>

// Problem constants
#define PB 2
#define PS 2048
#define PD 768
#define PC 8
#define PR 96
#define PH 16           // B*C
#define PM (PB*PS)      // 4096 flattened rows

// ---------------- scratch (device globals; no allocation allowed) -------------
__device__ float g_u [PM*PD];          // qz @ U^T   [B*S, D]
__device__ float g_v [PM*PD];          // qz @ V^T
__device__ float g_ur[PH*PS*PR];       // rope(qz_u)    [H,S,R]
__device__ float g_uo[PH*PS*PR];       // rope_o(qz_u)
__device__ float g_vr[PH*PS*PR];       // rope(qz_v)
__device__ float g_P [(size_t)PH*PS*PS]; // logits -> probs (268 MB)
__device__ float g_o1[PH*PS*PR];       // P  @ vr
__device__ float g_o2[PH*PS*PR];       // P^T @ uo
__device__ float g_g1[PM*PD];          // rope_o(o1) in [B*S, D]
__device__ float g_g2[PM*PD];          // rope  (o2) in [B*S, D]
__device__ float g_Ut[PD*PD];          // U^T
__device__ float g_Vt[PD*PD];          // V^T

// ---------------- 768x768 transpose ----------------
__global__ void transpose768(const float* __restrict__ src, float* __restrict__ dst) {
    __shared__ float t[32][33];
    int bx = blockIdx.x * 32, by = blockIdx.y * 32;
    int x = bx + threadIdx.x;
    #pragma unroll
    for (int i = 0; i < 32; i += 8) {
        int y = by + threadIdx.y + i;
        t[threadIdx.y + i][threadIdx.x] = src[y * PD + x];
    }
    __syncthreads();
    x = by + threadIdx.x;
    #pragma unroll
    for (int i = 0; i < 32; i += 8) {
        int y = bx + threadIdx.y + i;
        dst[y * PD + x] = t[threadIdx.x][threadIdx.y + i];
    }
}

// ---------------- generic NT GEMM: C[m,n] = alpha * sum_k A[m,k]*B[n,k] ------
// Requires M%128==0, N%128==0, K%8==0. Batched via blockIdx.z strides.
__global__ __launch_bounds__(256) void gemm_nt(
    const float* __restrict__ A, const float* __restrict__ B, float* __restrict__ C,
    int M, int N, int K,
    long long sA, long long sB, long long sC,
    float alpha, int accum)
{
    A += (long long)blockIdx.z * sA;
    B += (long long)blockIdx.z * sB;
    C += (long long)blockIdx.z * sC;

    __shared__ float As[8][128];
    __shared__ float Bs[8][128];

    const int tid = threadIdx.x;
    const int bm = blockIdx.y * 128;
    const int bn = blockIdx.x * 128;
    const int lr = tid >> 1;          // 0..127
    const int lc = (tid & 1) * 4;     // 0 or 4
    const int tx = tid & 15;
    const int ty = tid >> 4;

    const float* Aptr = A + (long long)(bm + lr) * K + lc;
    const float* Bptr = B + (long long)(bn + lr) * K + lc;

    float acc[8][8];
    #pragma unroll
    for (int i = 0; i < 8; i++)
        #pragma unroll
        for (int j = 0; j < 8; j++) acc[i][j] = 0.f;

    for (int k0 = 0; k0 < K; k0 += 8) {
        float4 av = *(const float4*)(Aptr + k0);
        float4 bv = *(const float4*)(Bptr + k0);
        __syncthreads();
        As[lc+0][lr] = av.x; As[lc+1][lr] = av.y; As[lc+2][lr] = av.z; As[lc+3][lr] = av.w;
        Bs[lc+0][lr] = bv.x; Bs[lc+1][lr] = bv.y; Bs[lc+2][lr] = bv.z; Bs[lc+3][lr] = bv.w;
        __syncthreads();
        #pragma unroll
        for (int k = 0; k < 8; k++) {
            float af[8], bf[8];
            *(float4*)&af[0] = *(const float4*)&As[k][ty*8];
            *(float4*)&af[4] = *(const float4*)&As[k][ty*8+4];
            *(float4*)&bf[0] = *(const float4*)&Bs[k][tx*8];
            *(float4*)&bf[4] = *(const float4*)&Bs[k][tx*8+4];
            #pragma unroll
            for (int i = 0; i < 8; i++)
                #pragma unroll
                for (int j = 0; j < 8; j++)
                    acc[i][j] = fmaf(af[i], bf[j], acc[i][j]);
        }
    }

    #pragma unroll
    for (int i = 0; i < 8; i++) {
        long long row = bm + ty*8 + i;
        #pragma unroll
        for (int j = 0; j < 8; j += 4) {
            long long idx = row * N + bn + tx*8 + j;
            float4 v;
            v.x = alpha * acc[i][j+0];
            v.y = alpha * acc[i][j+1];
            v.z = alpha * acc[i][j+2];
            v.w = alpha * acc[i][j+3];
            if (accum) {
                float4 o = *(const float4*)&C[idx];
                v.x += o.x; v.y += o.y; v.z += o.z; v.w += o.w;
            }
            *(float4*)&C[idx] = v;
        }
    }
}

// ---------------- RoPE forward: g_u/g_v -> ur, uo, vr ([H,S,R]) --------------
__global__ void rope_fwd(const float* __restrict__ cosp, const float* __restrict__ sinp) {
    int idx = blockIdx.x * blockDim.x + threadIdx.x;
    if (idx >= PH*PS*PR) return;
    int r = idx % PR;
    int s = (idx / PR) % PS;
    int h = idx / (PR*PS);
    int b = h >> 3, c = h & 7;

    long long base = ((long long)(b*PS + s)) * PD + c*PR;
    int   r2  = (r < PR/2) ? r + PR/2 : r - PR/2;
    float sgn = (r < PR/2) ? -1.f : 1.f;

    float xu  = g_u[base + r];
    float xur = sgn * g_u[base + r2];
    float xv  = g_v[base + r];
    float xvr = sgn * g_v[base + r2];

    long long ci = ((long long)(b*PS + s)) * PR + r;
    float cs = cosp[ci], sn = sinp[ci];

    g_ur[idx] = xu*cs + xur*sn;
    g_uo[idx] = xu*cs - xur*sn;
    g_vr[idx] = xv*cs + xvr*sn;
}

// ---------------- row softmax over g_P (rows of 2048) ------------------------
__global__ __launch_bounds__(256) void softmax_rows() {
    size_t row = blockIdx.x;
    float* p = g_P + row * PS;
    int t = threadIdx.x;

    float vals[8];
    float lm = -INFINITY;
    #pragma unroll
    for (int i = 0; i < 8; i++) { vals[i] = p[t + 256*i]; lm = fmaxf(lm, vals[i]); }

    __shared__ float red[8];
    // max reduce
    #pragma unroll
    for (int o = 16; o > 0; o >>= 1) lm = fmaxf(lm, __shfl_xor_sync(0xffffffffu, lm, o));
    if ((t & 31) == 0) red[t >> 5] = lm;
    __syncthreads();
    float m = fmaxf(fmaxf(fmaxf(red[0], red[1]), fmaxf(red[2], red[3])),
                    fmaxf(fmaxf(red[4], red[5]), fmaxf(red[6], red[7])));

    float ls = 0.f;
    #pragma unroll
    for (int i = 0; i < 8; i++) { vals[i] = __expf(vals[i] - m); ls += vals[i]; }
    #pragma unroll
    for (int o = 16; o > 0; o >>= 1) ls += __shfl_xor_sync(0xffffffffu, ls, o);
    __syncthreads();
    if ((t & 31) == 0) red[t >> 5] = ls;
    __syncthreads();
    float ssum = red[0]+red[1]+red[2]+red[3]+red[4]+red[5]+red[6]+red[7];
    float inv = 1.f / ssum;
    #pragma unroll
    for (int i = 0; i < 8; i++) p[t + 256*i] = vals[i] * inv;
}

// ---------------- PV GEMM: O = op(P) @ W, per head ---------------------------
// O [S,R], W [S,R]; transP=0: O[q,r]=sum_k P[q,k]W[k,r]; transP=1: O[q,r]=sum_k P[k,q]W[k,r]
__global__ __launch_bounds__(256) void pv_gemm(
    const float* __restrict__ Wfull, float* __restrict__ Ofull, int transP)
{
    const int h = blockIdx.y;
    const float* P  = g_P + (size_t)h * PS * PS;
    const float* W  = Wfull + (size_t)h * PS * PR;
    float*       O  = Ofull + (size_t)h * PS * PR;
    const int bm = blockIdx.x * 128;

    __shared__ float Ps[128][17];   // [q][k] padded
    __shared__ float Ws[16][PR];    // [k][r]

    const int tid = threadIdx.x;
    const int ty = tid >> 4;   // q group: 8 rows each
    const int tx = tid & 15;   // r group: 6 cols each

    float acc[8][6];
    #pragma unroll
    for (int i = 0; i < 8; i++)
        #pragma unroll
        for (int j = 0; j < 6; j++) acc[i][j] = 0.f;

    for (int k0 = 0; k0 < PS; k0 += 16) {
        float4 v0, v1;
        int sq, sc;
        if (!transP) {
            int q = tid >> 1, c = (tid & 1) * 8;
            const float* src = &P[(size_t)(bm + q) * PS + k0 + c];
            v0 = *(const float4*)(src);
            v1 = *(const float4*)(src + 4);
            sq = q; sc = c;
        } else {
            int kk = tid >> 4, c = (tid & 15) * 8;
            const float* src = &P[(size_t)(k0 + kk) * PS + bm + c];
            v0 = *(const float4*)(src);
            v1 = *(const float4*)(src + 4);
            sq = c; sc = kk;   // store transposed: Ps[c+i][kk]
        }
        __syncthreads();
        if (!transP) {
            Ps[sq][sc+0]=v0.x; Ps[sq][sc+1]=v0.y; Ps[sq][sc+2]=v0.z; Ps[sq][sc+3]=v0.w;
            Ps[sq][sc+4]=v1.x; Ps[sq][sc+5]=v1.y; Ps[sq][sc+6]=v1.z; Ps[sq][sc+7]=v1.w;
        } else {
            Ps[sq+0][sc]=v0.x; Ps[sq+1][sc]=v0.y; Ps[sq+2][sc]=v0.z; Ps[sq+3][sc]=v0.w;
            Ps[sq+4][sc]=v1.x; Ps[sq+5][sc]=v1.y; Ps[sq+6][sc]=v1.z; Ps[sq+7][sc]=v1.w;
        }
        // W tile 16 x 96
        #pragma unroll
        for (int e = tid; e < 16*PR; e += 256) {
            int k = e / PR, r = e % PR;
            Ws[k][r] = W[(size_t)(k0 + k) * PR + r];
        }
        __syncthreads();
        #pragma unroll
        for (int k = 0; k < 16; k++) {
            float a[8], bv[6];
            #pragma unroll
            for (int i = 0; i < 8; i++) a[i] = Ps[ty*8 + i][k];
            #pragma unroll
            for (int j = 0; j < 6; j++) bv[j] = Ws[k][tx*6 + j];
            #pragma unroll
            for (int i = 0; i < 8; i++)
                #pragma unroll
                for (int j = 0; j < 6; j++)
                    acc[i][j] = fmaf(a[i], bv[j], acc[i][j]);
        }
    }
    #pragma unroll
    for (int i = 0; i < 8; i++)
        #pragma unroll
        for (int j = 0; j < 6; j++)
            O[(size_t)(bm + ty*8 + i) * PR + tx*6 + j] = acc[i][j];
}

// ---------------- un-RoPE + reassemble to [B*S, D] ---------------------------
__global__ void rope_bwd(const float* __restrict__ cosp, const float* __restrict__ sinp) {
    int idx = blockIdx.x * blockDim.x + threadIdx.x;
    if (idx >= PH*PS*PR) return;
    int r = idx % PR;
    int s = (idx / PR) % PS;
    int h = idx / (PR*PS);
    int b = h >> 3, c = h & 7;

    int   r2  = (r < PR/2) ? r + PR/2 : r - PR/2;
    float sgn = (r < PR/2) ? -1.f : 1.f;
    int idx2 = idx - r + r2;

    long long ci = ((long long)(b*PS + s)) * PR + r;
    float cs = cosp[ci], sn = sinp[ci];

    float o1  = g_o1[idx],  o1r = sgn * g_o1[idx2];
    float o2  = g_o2[idx],  o2r = sgn * g_o2[idx2];

    long long dst = ((long long)(b*PS + s)) * PD + c*PR + r;
    g_g1[dst] = o1*cs - o1r*sn;   // rope_o
    g_g2[dst] = o2*cs + o2r*sn;   // rope
}

// ---------------- launch --------------------------------------------------
extern "C" void kernel_launch(void* const* d_in, const int* in_sizes, int n_in,
                              void* d_out, int out_size) {
    const float* qz  = (const float*)d_in[0];
    const float* cs  = (const float*)d_in[1];
    const float* sn  = (const float*)d_in[2];
    const float* U   = (const float*)d_in[3];
    const float* V   = (const float*)d_in[4];
    float* out = (float*)d_out;

    float *pu, *pv, *pur, *puo, *pvr, *pP, *po1, *po2, *pg1, *pg2, *pUt, *pVt;
    cudaGetSymbolAddress((void**)&pu,  g_u);
    cudaGetSymbolAddress((void**)&pv,  g_v);
    cudaGetSymbolAddress((void**)&pur, g_ur);
    cudaGetSymbolAddress((void**)&puo, g_uo);
    cudaGetSymbolAddress((void**)&pvr, g_vr);
    cudaGetSymbolAddress((void**)&pP,  g_P);
    cudaGetSymbolAddress((void**)&po1, g_o1);
    cudaGetSymbolAddress((void**)&po2, g_o2);
    cudaGetSymbolAddress((void**)&pg1, g_g1);
    cudaGetSymbolAddress((void**)&pg2, g_g2);
    cudaGetSymbolAddress((void**)&pUt, g_Ut);
    cudaGetSymbolAddress((void**)&pVt, g_Vt);

    dim3 tb(32, 8);
    dim3 tg(PD/32, PD/32);
    transpose768<<<tg, tb>>>(U, pUt);
    transpose768<<<tg, tb>>>(V, pVt);

    // input GEMMs: [4096,768] x [768,768]^T (NT; U rows already K-major)
    gemm_nt<<<dim3(PD/128, PM/128, 1), 256>>>(qz, U, pu, PM, PD, PD, 0, 0, 0, 1.f, 0);
    gemm_nt<<<dim3(PD/128, PM/128, 1), 256>>>(qz, V, pv, PM, PD, PD, 0, 0, 0, 1.f, 0);

    // RoPE
    {
        int n = PH*PS*PR;
        rope_fwd<<<(n + 255)/256, 256>>>(cs, sn);
    }

    // QK per head: L = 768 * ur @ vr^T
    gemm_nt<<<dim3(PS/128, PS/128, PH), 256>>>(
        pur, pvr, pP, PS, PS, PR,
        (long long)PS*PR, (long long)PS*PR, (long long)PS*PS, (float)PD, 0);

    // softmax rows
    softmax_rows<<<PH*PS, 256>>>();

    // PV: o1 = P @ vr ; o2 = P^T @ uo
    pv_gemm<<<dim3(PS/128, PH), 256>>>(pvr, po1, 0);
    pv_gemm<<<dim3(PS/128, PH), 256>>>(puo, po2, 1);

    // un-RoPE + reassemble
    {
        int n = PH*PS*PR;
        rope_bwd<<<(n + 255)/256, 256>>>(cs, sn);
    }

    // output GEMMs: out = g1 @ U + g2 @ V   (NT against U^T, V^T)
    gemm_nt<<<dim3(PD/128, PM/128, 1), 256>>>(pg1, pUt, out, PM, PD, PD, 0, 0, 0, 1.f, 0);
    gemm_nt<<<dim3(PD/128, PM/128, 1), 256>>>(pg2, pVt, out, PM, PD, PD, 0, 0, 0, 1.f, 1);
}

// round 2
// speedup vs baseline: 1.2797x; 1.2797x over previous
#include <cuda_runtime.h>
#include <math.h>

// Problem constants
#define PB 2
#define PS 2048
#define PD 768
#define PC 8
#define PR 96
#define PH 16            // B*C
#define PM (PB*PS)       // 4096
#define PD2 (2*PD)       // 1536

// ---------------- scratch (device globals) ----------------
__device__ float g_uv [(size_t)PM*PD2];    // [qz@U^T | qz@V^T]   [M,1536]
__device__ float g_ur [PH*PS*PR];          // rope(qz_u)   [H,S,R]
__device__ float g_uo [PH*PS*PR];          // rope_o(qz_u)
__device__ float g_vr [PH*PS*PR];          // rope(qz_v)
__device__ float g_P  [(size_t)PH*PS*PS];  // logits -> probs (268 MB)
__device__ float g_o1 [PH*PS*PR];          // P   @ vr
__device__ float g_o2 [PH*PS*PR];          // P^T @ uo
__device__ float g_g12[(size_t)PM*PD2];    // [rope_o(o1) | rope(o2)]  [M,1536]
__device__ float g_Wt [(size_t)PD*PD2];    // [U^T | V^T]  NT layout [768,1536]

// ---------------- 768x768 transpose into strided dst ----------------
__global__ void transpose768(const float* __restrict__ src, float* __restrict__ dst,
                             int dstStride, int dstOff) {
    __shared__ float t[32][33];
    int bx = blockIdx.x * 32, by = blockIdx.y * 32;
    int x = bx + threadIdx.x;
    #pragma unroll
    for (int i = 0; i < 32; i += 8) {
        int y = by + threadIdx.y + i;
        t[threadIdx.y + i][threadIdx.x] = src[y * PD + x];
    }
    __syncthreads();
    x = by + threadIdx.x;
    #pragma unroll
    for (int i = 0; i < 32; i += 8) {
        int row = bx + threadIdx.y + i;
        dst[(long long)row * dstStride + dstOff + x] = t[threadIdx.x][threadIdx.y + i];
    }
}

// ---------------- double-buffered NT GEMM -----------------------------------
// C[m,n] = alpha * sum_k A[m,k]*Brow(n)[k].  Brow(n) = B if n<Nsplit else B2[n-Nsplit].
// M%128==0, N%128==0, K%8==0. Batched via blockIdx.z strides.
__global__ __launch_bounds__(256) void gemm_nt(
    const float* __restrict__ A, const float* __restrict__ B,
    const float* __restrict__ B2, int Nsplit,
    float* __restrict__ C,
    int M, int N, int K,
    long long sA, long long sB, long long sC,
    float alpha)
{
    A += (long long)blockIdx.z * sA;
    B += (long long)blockIdx.z * sB;
    C += (long long)blockIdx.z * sC;

    __shared__ float As[2][8][132];
    __shared__ float Bs[2][8][132];

    const int tid = threadIdx.x;
    const int bm = blockIdx.y * 128;
    const int bn = blockIdx.x * 128;

    const float* Bbase; int bnn;
    if (bn < Nsplit) { Bbase = B;  bnn = bn; }
    else             { Bbase = B2; bnn = bn - Nsplit; }

    const int lr = tid >> 1;          // 0..127
    const int lc = (tid & 1) * 4;     // 0 or 4
    const int tx = tid & 15;
    const int ty = tid >> 4;

    const float* Aptr = A + (long long)(bm + lr) * K + lc;
    const float* Bptr = Bbase + (long long)(bnn + lr) * K + lc;

    float acc[8][8];
    #pragma unroll
    for (int i = 0; i < 8; i++)
        #pragma unroll
        for (int j = 0; j < 8; j++) acc[i][j] = 0.f;

    // prologue: load tile 0
    {
        float4 av = *(const float4*)(Aptr);
        float4 bv = *(const float4*)(Bptr);
        As[0][lc+0][lr] = av.x; As[0][lc+1][lr] = av.y;
        As[0][lc+2][lr] = av.z; As[0][lc+3][lr] = av.w;
        Bs[0][lc+0][lr] = bv.x; Bs[0][lc+1][lr] = bv.y;
        Bs[0][lc+2][lr] = bv.z; Bs[0][lc+3][lr] = bv.w;
    }
    __syncthreads();

    int buf = 0;
    for (int k0 = 8; k0 < K; k0 += 8) {
        float4 av = *(const float4*)(Aptr + k0);
        float4 bv = *(const float4*)(Bptr + k0);
        #pragma unroll
        for (int k = 0; k < 8; k++) {
            float af[8], bf[8];
            *(float4*)&af[0] = *(const float4*)&As[buf][k][ty*4];
            *(float4*)&af[4] = *(const float4*)&As[buf][k][64 + ty*4];
            *(float4*)&bf[0] = *(const float4*)&Bs[buf][k][tx*4];
            *(float4*)&bf[4] = *(const float4*)&Bs[buf][k][64 + tx*4];
            #pragma unroll
            for (int i = 0; i < 8; i++)
                #pragma unroll
                for (int j = 0; j < 8; j++)
                    acc[i][j] = fmaf(af[i], bf[j], acc[i][j]);
        }
        int nb = buf ^ 1;
        As[nb][lc+0][lr] = av.x; As[nb][lc+1][lr] = av.y;
        As[nb][lc+2][lr] = av.z; As[nb][lc+3][lr] = av.w;
        Bs[nb][lc+0][lr] = bv.x; Bs[nb][lc+1][lr] = bv.y;
        Bs[nb][lc+2][lr] = bv.z; Bs[nb][lc+3][lr] = bv.w;
        __syncthreads();
        buf = nb;
    }
    // final tile
    #pragma unroll
    for (int k = 0; k < 8; k++) {
        float af[8], bf[8];
        *(float4*)&af[0] = *(const float4*)&As[buf][k][ty*4];
        *(float4*)&af[4] = *(const float4*)&As[buf][k][64 + ty*4];
        *(float4*)&bf[0] = *(const float4*)&Bs[buf][k][tx*4];
        *(float4*)&bf[4] = *(const float4*)&Bs[buf][k][64 + tx*4];
        #pragma unroll
        for (int i = 0; i < 8; i++)
            #pragma unroll
            for (int j = 0; j < 8; j++)
                acc[i][j] = fmaf(af[i], bf[j], acc[i][j]);
    }

    // epilogue
    #pragma unroll
    for (int i = 0; i < 8; i++) {
        int row = bm + ((i < 4) ? (ty*4 + i) : (64 + ty*4 + (i-4)));
        #pragma unroll
        for (int jg = 0; jg < 2; jg++) {
            int col = bn + (jg == 0 ? tx*4 : 64 + tx*4);
            float4 v;
            v.x = alpha * acc[i][jg*4+0];
            v.y = alpha * acc[i][jg*4+1];
            v.z = alpha * acc[i][jg*4+2];
            v.w = alpha * acc[i][jg*4+3];
            *(float4*)&C[(long long)row * N + col] = v;
        }
    }
}

// ---------------- RoPE forward: g_uv -> ur, uo, vr ([H,S,R]) -----------------
__global__ void rope_fwd(const float* __restrict__ cosp, const float* __restrict__ sinp) {
    int idx = blockIdx.x * blockDim.x + threadIdx.x;
    if (idx >= PH*PS*PR) return;
    int r = idx % PR;
    int s = (idx / PR) % PS;
    int h = idx / (PR*PS);
    int b = h >> 3, c = h & 7;

    long long base = ((long long)(b*PS + s)) * PD2 + c*PR;
    int   r2  = (r < PR/2) ? r + PR/2 : r - PR/2;
    float sgn = (r < PR/2) ? -1.f : 1.f;

    float xu  = g_uv[base + r];
    float xur = sgn * g_uv[base + r2];
    float xv  = g_uv[base + PD + r];
    float xvr = sgn * g_uv[base + PD + r2];

    long long ci = ((long long)(b*PS + s)) * PR + r;
    float cs = cosp[ci], sn = sinp[ci];

    g_ur[idx] = xu*cs + xur*sn;
    g_uo[idx] = xu*cs - xur*sn;
    g_vr[idx] = xv*cs + xvr*sn;
}

// ---------------- row softmax over g_P (rows of 2048) ------------------------
__global__ __launch_bounds__(256) void softmax_rows() {
    size_t row = blockIdx.x;
    float4* p = (float4*)(g_P + row * PS);
    int t = threadIdx.x;

    float4 v0 = p[t], v1 = p[t + 256];
    float lm = fmaxf(fmaxf(fmaxf(v0.x, v0.y), fmaxf(v0.z, v0.w)),
                     fmaxf(fmaxf(v1.x, v1.y), fmaxf(v1.z, v1.w)));

    __shared__ float red[8];
    #pragma unroll
    for (int o = 16; o > 0; o >>= 1) lm = fmaxf(lm, __shfl_xor_sync(0xffffffffu, lm, o));
    if ((t & 31) == 0) red[t >> 5] = lm;
    __syncthreads();
    float m = fmaxf(fmaxf(fmaxf(red[0], red[1]), fmaxf(red[2], red[3])),
                    fmaxf(fmaxf(red[4], red[5]), fmaxf(red[6], red[7])));

    v0.x = __expf(v0.x - m); v0.y = __expf(v0.y - m);
    v0.z = __expf(v0.z - m); v0.w = __expf(v0.w - m);
    v1.x = __expf(v1.x - m); v1.y = __expf(v1.y - m);
    v1.z = __expf(v1.z - m); v1.w = __expf(v1.w - m);
    float ls = v0.x+v0.y+v0.z+v0.w + v1.x+v1.y+v1.z+v1.w;
    #pragma unroll
    for (int o = 16; o > 0; o >>= 1) ls += __shfl_xor_sync(0xffffffffu, ls, o);
    __syncthreads();
    if ((t & 31) == 0) red[t >> 5] = ls;
    __syncthreads();
    float inv = 1.f / (red[0]+red[1]+red[2]+red[3]+red[4]+red[5]+red[6]+red[7]);
    v0.x *= inv; v0.y *= inv; v0.z *= inv; v0.w *= inv;
    v1.x *= inv; v1.y *= inv; v1.z *= inv; v1.w *= inv;
    p[t] = v0; p[t + 256] = v1;
}

// ---------------- merged PV GEMM ---------------------------------------------
// z==0: o1[q,r] = sum_k P[q,k]*vr[k,r];  z==1: o2[q,r] = sum_k P[k,q]*uo[k,r]
__global__ __launch_bounds__(256) void pv_gemm(
    const float* __restrict__ vr, const float* __restrict__ uo,
    float* __restrict__ o1, float* __restrict__ o2)
{
    const int transP = blockIdx.z;
    const int h = blockIdx.y;
    const float* P = g_P + (size_t)h * PS * PS;
    const float* W = (transP ? uo : vr) + (size_t)h * PS * PR;
    float*       O = (transP ? o2 : o1) + (size_t)h * PS * PR;
    const int bm = blockIdx.x * 128;

    __shared__ float Ps[2][16][136];  // [k][q]
    __shared__ float Ws[2][16][PR];   // [k][r]

    const int tid = threadIdx.x;
    const int ty = tid >> 3;   // 0..31, 4 q-rows each
    const int tx = tid & 7;    // 0..7, 12 r-cols each

    const int lq  = tid >> 1,  lc0 = (tid & 1) * 8;   // trans=0 loader
    const int lk  = tid >> 4,  lc1 = (tid & 15) * 8;  // trans=1 loader
    const int wk  = (tid * 6) / PR, wr = (tid * 6) % PR;

    float acc[4][12];
    #pragma unroll
    for (int i = 0; i < 4; i++)
        #pragma unroll
        for (int j = 0; j < 12; j++) acc[i][j] = 0.f;

    float4 v0, v1;
    float wreg[6];

    // prologue load
    if (!transP) {
        const float* s = &P[(size_t)(bm + lq) * PS + lc0];
        v0 = *(const float4*)s; v1 = *(const float4*)(s + 4);
    } else {
        const float* s = &P[(size_t)lk * PS + bm + lc1];
        v0 = *(const float4*)s; v1 = *(const float4*)(s + 4);
    }
    #pragma unroll
    for (int i = 0; i < 6; i++) wreg[i] = W[(size_t)wk * PR + wr + i];

    if (!transP) {
        Ps[0][lc0+0][lq]=v0.x; Ps[0][lc0+1][lq]=v0.y; Ps[0][lc0+2][lq]=v0.z; Ps[0][lc0+3][lq]=v0.w;
        Ps[0][lc0+4][lq]=v1.x; Ps[0][lc0+5][lq]=v1.y; Ps[0][lc0+6][lq]=v1.z; Ps[0][lc0+7][lq]=v1.w;
    } else {
        *(float4*)&Ps[0][lk][lc1] = v0; *(float4*)&Ps[0][lk][lc1+4] = v1;
    }
    #pragma unroll
    for (int i = 0; i < 6; i++) Ws[0][wk][wr+i] = wreg[i];
    __syncthreads();

    int buf = 0;
    for (int k0 = 16; k0 < PS; k0 += 16) {
        // prefetch
        if (!transP) {
            const float* s = &P[(size_t)(bm + lq) * PS + k0 + lc0];
            v0 = *(const float4*)s; v1 = *(const float4*)(s + 4);
        } else {
            const float* s = &P[(size_t)(k0 + lk) * PS + bm + lc1];
            v0 = *(const float4*)s; v1 = *(const float4*)(s + 4);
        }
        #pragma unroll
        for (int i = 0; i < 6; i++) wreg[i] = W[(size_t)(k0 + wk) * PR + wr + i];

        // compute current
        #pragma unroll
        for (int k = 0; k < 16; k++) {
            float4 a = *(const float4*)&Ps[buf][k][ty*4];
            float bfr[12];
            *(float4*)&bfr[0] = *(const float4*)&Ws[buf][k][tx*12];
            *(float4*)&bfr[4] = *(const float4*)&Ws[buf][k][tx*12+4];
            *(float4*)&bfr[8] = *(const float4*)&Ws[buf][k][tx*12+8];
            #pragma unroll
            for (int j = 0; j < 12; j++) {
                acc[0][j] = fmaf(a.x, bfr[j], acc[0][j]);
                acc[1][j] = fmaf(a.y, bfr[j], acc[1][j]);
                acc[2][j] = fmaf(a.z, bfr[j], acc[2][j]);
                acc[3][j] = fmaf(a.w, bfr[j], acc[3][j]);
            }
        }

        int nb = buf ^ 1;
        if (!transP) {
            Ps[nb][lc0+0][lq]=v0.x; Ps[nb][lc0+1][lq]=v0.y; Ps[nb][lc0+2][lq]=v0.z; Ps[nb][lc0+3][lq]=v0.w;
            Ps[nb][lc0+4][lq]=v1.x; Ps[nb][lc0+5][lq]=v1.y; Ps[nb][lc0+6][lq]=v1.z; Ps[nb][lc0+7][lq]=v1.w;
        } else {
            *(float4*)&Ps[nb][lk][lc1] = v0; *(float4*)&Ps[nb][lk][lc1+4] = v1;
        }
        #pragma unroll
        for (int i = 0; i < 6; i++) Ws[nb][wk][wr+i] = wreg[i];
        __syncthreads();
        buf = nb;
    }
    // last tile
    #pragma unroll
    for (int k = 0; k < 16; k++) {
        float4 a = *(const float4*)&Ps[buf][k][ty*4];
        float bfr[12];
        *(float4*)&bfr[0] = *(const float4*)&Ws[buf][k][tx*12];
        *(float4*)&bfr[4] = *(const float4*)&Ws[buf][k][tx*12+4];
        *(float4*)&bfr[8] = *(const float4*)&Ws[buf][k][tx*12+8];
        #pragma unroll
        for (int j = 0; j < 12; j++) {
            acc[0][j] = fmaf(a.x, bfr[j], acc[0][j]);
            acc[1][j] = fmaf(a.y, bfr[j], acc[1][j]);
            acc[2][j] = fmaf(a.z, bfr[j], acc[2][j]);
            acc[3][j] = fmaf(a.w, bfr[j], acc[3][j]);
        }
    }

    #pragma unroll
    for (int i = 0; i < 4; i++) {
        size_t rowoff = (size_t)(bm + ty*4 + i) * PR + tx*12;
        *(float4*)&O[rowoff]     = *(float4*)&acc[i][0];
        *(float4*)&O[rowoff + 4] = *(float4*)&acc[i][4];
        *(float4*)&O[rowoff + 8] = *(float4*)&acc[i][8];
    }
}

// ---------------- un-RoPE + reassemble to [M, 1536] --------------------------
__global__ void rope_bwd(const float* __restrict__ cosp, const float* __restrict__ sinp) {
    int idx = blockIdx.x * blockDim.x + threadIdx.x;
    if (idx >= PH*PS*PR) return;
    int r = idx % PR;
    int s = (idx / PR) % PS;
    int h = idx / (PR*PS);
    int b = h >> 3, c = h & 7;

    int   r2  = (r < PR/2) ? r + PR/2 : r - PR/2;
    float sgn = (r < PR/2) ? -1.f : 1.f;
    int idx2 = idx - r + r2;

    long long ci = ((long long)(b*PS + s)) * PR + r;
    float cs = cosp[ci], sn = sinp[ci];

    float o1  = g_o1[idx],  o1r = sgn * g_o1[idx2];
    float o2  = g_o2[idx],  o2r = sgn * g_o2[idx2];

    long long dst = ((long long)(b*PS + s)) * PD2 + c*PR + r;
    g_g12[dst]      = o1*cs - o1r*sn;   // rope_o
    g_g12[dst + PD] = o2*cs + o2r*sn;   // rope
}

// ---------------- launch ------------------------------------------------------
extern "C" void kernel_launch(void* const* d_in, const int* in_sizes, int n_in,
                              void* d_out, int out_size) {
    const float* qz  = (const float*)d_in[0];
    const float* cs  = (const float*)d_in[1];
    const float* sn  = (const float*)d_in[2];
    const float* U   = (const float*)d_in[3];
    const float* V   = (const float*)d_in[4];
    float* out = (float*)d_out;

    float *puv, *pur, *puo, *pvr, *pP, *po1, *po2, *pg12, *pWt;
    cudaGetSymbolAddress((void**)&puv,  g_uv);
    cudaGetSymbolAddress((void**)&pur,  g_ur);
    cudaGetSymbolAddress((void**)&puo,  g_uo);
    cudaGetSymbolAddress((void**)&pvr,  g_vr);
    cudaGetSymbolAddress((void**)&pP,   g_P);
    cudaGetSymbolAddress((void**)&po1,  g_o1);
    cudaGetSymbolAddress((void**)&po2,  g_o2);
    cudaGetSymbolAddress((void**)&pg12, g_g12);
    cudaGetSymbolAddress((void**)&pWt,  g_Wt);

    // build [U^T | V^T] with row stride 1536
    dim3 tb(32, 8), tg(PD/32, PD/32);
    transpose768<<<tg, tb>>>(U, pWt, PD2, 0);
    transpose768<<<tg, tb>>>(V, pWt, PD2, PD);

    // fused input GEMM: g_uv = qz @ [U^T | V^T]   (NT against U rows / V rows)
    gemm_nt<<<dim3(PD2/128, PM/128, 1), 256>>>(
        qz, U, V, PD, puv, PM, PD2, PD, 0, 0, 0, 1.f);

    // RoPE
    rope_fwd<<<(PH*PS*PR + 255)/256, 256>>>(cs, sn);

    // QK per head: L = 768 * ur @ vr^T
    gemm_nt<<<dim3(PS/128, PS/128, PH), 256>>>(
        pur, pvr, pvr, 1 << 30, pP, PS, PS, PR,
        (long long)PS*PR, (long long)PS*PR, (long long)PS*PS, (float)PD);

    // softmax rows
    softmax_rows<<<PH*PS, 256>>>();

    // merged PV: z=0 -> o1 = P @ vr ; z=1 -> o2 = P^T @ uo
    pv_gemm<<<dim3(PS/128, PH, 2), 256>>>(pvr, puo, po1, po2);

    // un-RoPE + reassemble into [g1 | g2]
    rope_bwd<<<(PH*PS*PR + 255)/256, 256>>>(cs, sn);

    // fused output GEMM: out = [g1 | g2] @ [U^T | V^T]^T(NT)  (K = 1536)
    gemm_nt<<<dim3(PD/128, PM/128, 1), 256>>>(
        pg12, pWt, pWt, 1 << 30, out, PM, PD, PD2, 0, 0, 0, 1.f);
}

// round 3
// speedup vs baseline: 2.1017x; 1.6423x over previous
#include <cuda_runtime.h>
#include <math.h>

// Problem constants
#define PB 2
#define PS 2048
#define PD 768
#define PC 8
#define PR 96
#define PH 16            // B*C
#define PM (PB*PS)       // 4096
#define PD2 (2*PD)       // 1536
#define CAP 64           // max candidates per row
#define NROWS (PH*PS)    // 32768 attention rows

// ---------------- scratch (device globals) ----------------
__device__ float g_uv [(size_t)PM*PD2];    // [qz@U^T | qz@V^T]   [M,1536]
__device__ float g_ur [PH*PS*PR];          // rope(qz_u)   [H,S,R]
__device__ float g_uo [PH*PS*PR];          // rope_o(qz_u)
__device__ float g_vr [PH*PS*PR];          // rope(qz_v)
__device__ float g_o1 [PH*PS*PR];          // P   @ vr
__device__ float g_o2 [PH*PS*PR];          // P^T @ uo
__device__ float g_g12[(size_t)PM*PD2];    // [rope_o(o1) | rope(o2)]  [M,1536]
__device__ float g_Wt [(size_t)PD*PD2];    // [U^T | V^T]  NT layout [768,1536]
__device__ int   g_cnt [NROWS];            // candidate counts
__device__ float g_cval[(size_t)NROWS*CAP];// candidate logits -> probs
__device__ int   g_ccol[(size_t)NROWS*CAP];// candidate columns

// ---------------- zero scratch (counts + o2 accumulator) ---------------------
__global__ void zero_scratch() {
    int i = blockIdx.x * blockDim.x + threadIdx.x;
    if (i < NROWS) g_cnt[i] = 0;
    if (i < PH*PS*PR) g_o2[i] = 0.f;
}

// ---------------- 768x768 transpose into strided dst ----------------
__global__ void transpose768(const float* __restrict__ src, float* __restrict__ dst,
                             int dstStride, int dstOff) {
    __shared__ float t[32][33];
    int bx = blockIdx.x * 32, by = blockIdx.y * 32;
    int x = bx + threadIdx.x;
    #pragma unroll
    for (int i = 0; i < 32; i += 8) {
        int y = by + threadIdx.y + i;
        t[threadIdx.y + i][threadIdx.x] = src[y * PD + x];
    }
    __syncthreads();
    x = by + threadIdx.x;
    #pragma unroll
    for (int i = 0; i < 32; i += 8) {
        int row = bx + threadIdx.y + i;
        dst[(long long)row * dstStride + dstOff + x] = t[threadIdx.x][threadIdx.y + i];
    }
}

// ---------------- double-buffered NT GEMM (dense projections) ----------------
// C[m,n] = sum_k A[m,k]*Brow(n)[k].  Brow(n) = B if n<Nsplit else B2[n-Nsplit].
__global__ __launch_bounds__(256) void gemm_nt(
    const float* __restrict__ A, const float* __restrict__ B,
    const float* __restrict__ B2, int Nsplit,
    float* __restrict__ C,
    int M, int N, int K)
{
    __shared__ float As[2][8][132];
    __shared__ float Bs[2][8][132];

    const int tid = threadIdx.x;
    const int bm = blockIdx.y * 128;
    const int bn = blockIdx.x * 128;

    const float* Bbase; int bnn;
    if (bn < Nsplit) { Bbase = B;  bnn = bn; }
    else             { Bbase = B2; bnn = bn - Nsplit; }

    const int lr = tid >> 1;
    const int lc = (tid & 1) * 4;
    const int tx = tid & 15;
    const int ty = tid >> 4;

    const float* Aptr = A + (long long)(bm + lr) * K + lc;
    const float* Bptr = Bbase + (long long)(bnn + lr) * K + lc;

    float acc[8][8];
    #pragma unroll
    for (int i = 0; i < 8; i++)
        #pragma unroll
        for (int j = 0; j < 8; j++) acc[i][j] = 0.f;

    {
        float4 av = *(const float4*)(Aptr);
        float4 bv = *(const float4*)(Bptr);
        As[0][lc+0][lr] = av.x; As[0][lc+1][lr] = av.y;
        As[0][lc+2][lr] = av.z; As[0][lc+3][lr] = av.w;
        Bs[0][lc+0][lr] = bv.x; Bs[0][lc+1][lr] = bv.y;
        Bs[0][lc+2][lr] = bv.z; Bs[0][lc+3][lr] = bv.w;
    }
    __syncthreads();

    int buf = 0;
    for (int k0 = 8; k0 < K; k0 += 8) {
        float4 av = *(const float4*)(Aptr + k0);
        float4 bv = *(const float4*)(Bptr + k0);
        #pragma unroll
        for (int k = 0; k < 8; k++) {
            float af[8], bf[8];
            *(float4*)&af[0] = *(const float4*)&As[buf][k][ty*4];
            *(float4*)&af[4] = *(const float4*)&As[buf][k][64 + ty*4];
            *(float4*)&bf[0] = *(const float4*)&Bs[buf][k][tx*4];
            *(float4*)&bf[4] = *(const float4*)&Bs[buf][k][64 + tx*4];
            #pragma unroll
            for (int i = 0; i < 8; i++)
                #pragma unroll
                for (int j = 0; j < 8; j++)
                    acc[i][j] = fmaf(af[i], bf[j], acc[i][j]);
        }
        int nb = buf ^ 1;
        As[nb][lc+0][lr] = av.x; As[nb][lc+1][lr] = av.y;
        As[nb][lc+2][lr] = av.z; As[nb][lc+3][lr] = av.w;
        Bs[nb][lc+0][lr] = bv.x; Bs[nb][lc+1][lr] = bv.y;
        Bs[nb][lc+2][lr] = bv.z; Bs[nb][lc+3][lr] = bv.w;
        __syncthreads();
        buf = nb;
    }
    #pragma unroll
    for (int k = 0; k < 8; k++) {
        float af[8], bf[8];
        *(float4*)&af[0] = *(const float4*)&As[buf][k][ty*4];
        *(float4*)&af[4] = *(const float4*)&As[buf][k][64 + ty*4];
        *(float4*)&bf[0] = *(const float4*)&Bs[buf][k][tx*4];
        *(float4*)&bf[4] = *(const float4*)&Bs[buf][k][64 + tx*4];
        #pragma unroll
        for (int i = 0; i < 8; i++)
            #pragma unroll
            for (int j = 0; j < 8; j++)
                acc[i][j] = fmaf(af[i], bf[j], acc[i][j]);
    }

    #pragma unroll
    for (int i = 0; i < 8; i++) {
        int row = bm + ((i < 4) ? (ty*4 + i) : (64 + ty*4 + (i-4)));
        #pragma unroll
        for (int jg = 0; jg < 2; jg++) {
            int col = bn + (jg == 0 ? tx*4 : 64 + tx*4);
            *(float4*)&C[(long long)row * N + col] = *(float4*)&acc[i][jg*4];
        }
    }
}

// ---------------- QK + candidate selection -----------------------------------
// Computes L = 768 * ur@vr^T per head tile (bit-identical math to dense path),
// appends entries with L >= local_rowmax - 25 to per-row candidate lists.
__global__ __launch_bounds__(256) void qk_select(
    const float* __restrict__ urp, const float* __restrict__ vrp)
{
    const int h = blockIdx.z;
    const float* A = urp + (size_t)h * PS * PR;
    const float* B = vrp + (size_t)h * PS * PR;

    __shared__ float As[2][8][132];
    __shared__ float Bs[2][8][132];

    const int tid = threadIdx.x;
    const int bm = blockIdx.y * 128;
    const int bn = blockIdx.x * 128;

    const int lr = tid >> 1;
    const int lc = (tid & 1) * 4;
    const int tx = tid & 15;
    const int ty = tid >> 4;

    const float* Aptr = A + (long long)(bm + lr) * PR + lc;
    const float* Bptr = B + (long long)(bn + lr) * PR + lc;

    float acc[8][8];
    #pragma unroll
    for (int i = 0; i < 8; i++)
        #pragma unroll
        for (int j = 0; j < 8; j++) acc[i][j] = 0.f;

    {
        float4 av = *(const float4*)(Aptr);
        float4 bv = *(const float4*)(Bptr);
        As[0][lc+0][lr] = av.x; As[0][lc+1][lr] = av.y;
        As[0][lc+2][lr] = av.z; As[0][lc+3][lr] = av.w;
        Bs[0][lc+0][lr] = bv.x; Bs[0][lc+1][lr] = bv.y;
        Bs[0][lc+2][lr] = bv.z; Bs[0][lc+3][lr] = bv.w;
    }
    __syncthreads();

    int buf = 0;
    for (int k0 = 8; k0 < PR; k0 += 8) {
        float4 av = *(const float4*)(Aptr + k0);
        float4 bv = *(const float4*)(Bptr + k0);
        #pragma unroll
        for (int k = 0; k < 8; k++) {
            float af[8], bf[8];
            *(float4*)&af[0] = *(const float4*)&As[buf][k][ty*4];
            *(float4*)&af[4] = *(const float4*)&As[buf][k][64 + ty*4];
            *(float4*)&bf[0] = *(const float4*)&Bs[buf][k][tx*4];
            *(float4*)&bf[4] = *(const float4*)&Bs[buf][k][64 + tx*4];
            #pragma unroll
            for (int i = 0; i < 8; i++)
                #pragma unroll
                for (int j = 0; j < 8; j++)
                    acc[i][j] = fmaf(af[i], bf[j], acc[i][j]);
        }
        int nb = buf ^ 1;
        As[nb][lc+0][lr] = av.x; As[nb][lc+1][lr] = av.y;
        As[nb][lc+2][lr] = av.z; As[nb][lc+3][lr] = av.w;
        Bs[nb][lc+0][lr] = bv.x; Bs[nb][lc+1][lr] = bv.y;
        Bs[nb][lc+2][lr] = bv.z; Bs[nb][lc+3][lr] = bv.w;
        __syncthreads();
        buf = nb;
    }
    #pragma unroll
    for (int k = 0; k < 8; k++) {
        float af[8], bf[8];
        *(float4*)&af[0] = *(const float4*)&As[buf][k][ty*4];
        *(float4*)&af[4] = *(const float4*)&As[buf][k][64 + ty*4];
        *(float4*)&bf[0] = *(const float4*)&Bs[buf][k][tx*4];
        *(float4*)&bf[4] = *(const float4*)&Bs[buf][k][64 + tx*4];
        #pragma unroll
        for (int i = 0; i < 8; i++)
            #pragma unroll
            for (int j = 0; j < 8; j++)
                acc[i][j] = fmaf(af[i], bf[j], acc[i][j]);
    }

    // selection epilogue: scale to logits, row-local max over 16 lanes, append
    const float SCALE = (float)PD;
    #pragma unroll
    for (int i = 0; i < 8; i++) {
        float rmax = -INFINITY;
        #pragma unroll
        for (int j = 0; j < 8; j++) {
            acc[i][j] *= SCALE;
            rmax = fmaxf(rmax, acc[i][j]);
        }
        // the 16 threads holding this row are a contiguous half-warp
        #pragma unroll
        for (int o = 1; o < 16; o <<= 1)
            rmax = fmaxf(rmax, __shfl_xor_sync(0xffffffffu, rmax, o));

        int row = bm + ((i < 4) ? (ty*4 + i) : (64 + ty*4 + (i-4)));
        long long rid = (long long)h * PS + row;
        float thr = rmax - 25.f;
        #pragma unroll
        for (int j = 0; j < 8; j++) {
            if (acc[i][j] >= thr) {
                int pos = atomicAdd(&g_cnt[rid], 1);
                if (pos < CAP) {
                    g_cval[rid*CAP + pos] = acc[i][j];
                    g_ccol[rid*CAP + pos] = bn + ((j < 4) ? (tx*4 + j) : (64 + tx*4 + (j-4)));
                }
            }
        }
    }
}

// ---------------- finalize: per-row softmax over candidates, compact ---------
__global__ void finalize_rows() {
    int row = blockIdx.x * blockDim.x + threadIdx.x;
    if (row >= NROWS) return;
    int cnt = g_cnt[row]; if (cnt > CAP) cnt = CAP;
    long long base = (long long)row * CAP;

    float gmax = -INFINITY;
    for (int i = 0; i < cnt; i++) gmax = fmaxf(gmax, g_cval[base + i]);
    float sum = 0.f;
    for (int i = 0; i < cnt; i++) sum += expf(g_cval[base + i] - gmax);
    float inv = 1.f / sum;
    int out = 0;
    for (int i = 0; i < cnt; i++) {
        float p = expf(g_cval[base + i] - gmax) * inv;
        if (p > 1e-12f) {
            g_cval[base + out] = p;
            g_ccol[base + out] = g_ccol[base + i];
            out++;
        }
    }
    g_cnt[row] = out;
}

// ---------------- sparse PV: o1 gather, o2 scatter ----------------------------
__global__ __launch_bounds__(96) void sparse_pv(
    const float* __restrict__ vrp, const float* __restrict__ uop)
{
    int row = blockIdx.x;             // h*PS + q
    int h = row >> 11;                // row / PS
    int r = threadIdx.x;              // 0..95
    long long base = (long long)row * CAP;
    int cnt = g_cnt[row];

    const float* vrh = vrp + (size_t)h * PS * PR;
    float myuo = uop[(size_t)row * PR + r];

    float acc = 0.f;
    for (int e = 0; e < cnt; e++) {
        float p = g_cval[base + e];
        int col = g_ccol[base + e];
        acc = fmaf(p, vrh[(size_t)col * PR + r], acc);
        atomicAdd(&g_o2[((size_t)h * PS + col) * PR + r], p * myuo);
    }
    g_o1[(size_t)row * PR + r] = acc;
}

// ---------------- RoPE forward: g_uv -> ur, uo, vr ([H,S,R]) -----------------
__global__ void rope_fwd(const float* __restrict__ cosp, const float* __restrict__ sinp) {
    int idx = blockIdx.x * blockDim.x + threadIdx.x;
    if (idx >= PH*PS*PR) return;
    int r = idx % PR;
    int s = (idx / PR) % PS;
    int h = idx / (PR*PS);
    int b = h >> 3, c = h & 7;

    long long base = ((long long)(b*PS + s)) * PD2 + c*PR;
    int   r2  = (r < PR/2) ? r + PR/2 : r - PR/2;
    float sgn = (r < PR/2) ? -1.f : 1.f;

    float xu  = g_uv[base + r];
    float xur = sgn * g_uv[base + r2];
    float xv  = g_uv[base + PD + r];
    float xvr = sgn * g_uv[base + PD + r2];

    long long ci = ((long long)(b*PS + s)) * PR + r;
    float cs = cosp[ci], sn = sinp[ci];

    g_ur[idx] = xu*cs + xur*sn;
    g_uo[idx] = xu*cs - xur*sn;
    g_vr[idx] = xv*cs + xvr*sn;
}

// ---------------- un-RoPE + reassemble to [M, 1536] --------------------------
__global__ void rope_bwd(const float* __restrict__ cosp, const float* __restrict__ sinp) {
    int idx = blockIdx.x * blockDim.x + threadIdx.x;
    if (idx >= PH*PS*PR) return;
    int r = idx % PR;
    int s = (idx / PR) % PS;
    int h = idx / (PR*PS);
    int b = h >> 3, c = h & 7;

    int   r2  = (r < PR/2) ? r + PR/2 : r - PR/2;
    float sgn = (r < PR/2) ? -1.f : 1.f;
    int idx2 = idx - r + r2;

    long long ci = ((long long)(b*PS + s)) * PR + r;
    float cs = cosp[ci], sn = sinp[ci];

    float o1  = g_o1[idx],  o1r = sgn * g_o1[idx2];
    float o2  = g_o2[idx],  o2r = sgn * g_o2[idx2];

    long long dst = ((long long)(b*PS + s)) * PD2 + c*PR + r;
    g_g12[dst]      = o1*cs - o1r*sn;   // rope_o
    g_g12[dst + PD] = o2*cs + o2r*sn;   // rope
}

// ---------------- launch ------------------------------------------------------
extern "C" void kernel_launch(void* const* d_in, const int* in_sizes, int n_in,
                              void* d_out, int out_size) {
    const float* qz  = (const float*)d_in[0];
    const float* cs  = (const float*)d_in[1];
    const float* sn  = (const float*)d_in[2];
    const float* U   = (const float*)d_in[3];
    const float* V   = (const float*)d_in[4];
    float* out = (float*)d_out;

    float *puv, *pur, *puo, *pvr, *po1, *po2, *pg12, *pWt;
    cudaGetSymbolAddress((void**)&puv,  g_uv);
    cudaGetSymbolAddress((void**)&pur,  g_ur);
    cudaGetSymbolAddress((void**)&puo,  g_uo);
    cudaGetSymbolAddress((void**)&pvr,  g_vr);
    cudaGetSymbolAddress((void**)&po1,  g_o1);
    cudaGetSymbolAddress((void**)&po2,  g_o2);
    cudaGetSymbolAddress((void**)&pg12, g_g12);
    cudaGetSymbolAddress((void**)&pWt,  g_Wt);

    // zero candidate counts + o2 accumulator
    zero_scratch<<<(PH*PS*PR + 255)/256, 256>>>();

    // build [U^T | V^T] with row stride 1536
    dim3 tb(32, 8), tg(PD/32, PD/32);
    transpose768<<<tg, tb>>>(U, pWt, PD2, 0);
    transpose768<<<tg, tb>>>(V, pWt, PD2, PD);

    // fused input GEMM: g_uv = qz @ [U^T | V^T]
    gemm_nt<<<dim3(PD2/128, PM/128, 1), 256>>>(qz, U, V, PD, puv, PM, PD2, PD);

    // RoPE
    rope_fwd<<<(PH*PS*PR + 255)/256, 256>>>(cs, sn);

    // QK + candidate selection (no P materialization)
    qk_select<<<dim3(PS/128, PS/128, PH), 256>>>(pur, pvr);

    // per-row softmax over candidates
    finalize_rows<<<(NROWS + 127)/128, 128>>>();

    // sparse PV: o1 gather + o2 scatter
    sparse_pv<<<NROWS, 96>>>(pvr, puo);

    // un-RoPE + reassemble into [g1 | g2]
    rope_bwd<<<(PH*PS*PR + 255)/256, 256>>>(cs, sn);

    // fused output GEMM: out = [g1 | g2] @ [Wt rows]  (K = 1536)
    gemm_nt<<<dim3(PD/128, PM/128, 1), 256>>>(pg12, pWt, pWt, 1 << 30, out, PM, PD, PD2);
}

// round 5
// speedup vs baseline: 2.3990x; 1.1414x over previous
#include <cuda_runtime.h>
#include <cuda_bf16.h>
#include <math.h>
#include <stdint.h>

// Problem constants
#define PB 2
#define PS 2048
#define PD 768
#define PC 8
#define PR 96
#define PH 16            // B*C
#define PM (PB*PS)       // 4096
#define PD2 (2*PD)       // 1536
#define CAP 64           // max candidates per row
#define NROWS (PH*PS)    // 32768 attention rows

// ---------------- scratch (device globals) ----------------
__device__ float g_uv [(size_t)PM*PD2];    // [qz@U^T | qz@V^T]   [M,1536]
__device__ float g_ur [PH*PS*PR];          // rope(qz_u)   [H,S,R]
__device__ float g_uo [PH*PS*PR];          // rope_o(qz_u)
__device__ float g_vr [PH*PS*PR];          // rope(qz_v)
__device__ float g_o1 [PH*PS*PR];          // P   @ vr
__device__ float g_o2 [PH*PS*PR];          // P^T @ uo
__device__ float g_g12[(size_t)PM*PD2];    // [rope_o(o1) | rope(o2)]  [M,1536]
__device__ float g_Wt [(size_t)PD*PD2];    // [U^T | V^T]  NT layout [768,1536]
__device__ int   g_cnt [NROWS];            // candidate counts
__device__ float g_cval[(size_t)NROWS*CAP];// exact candidate logits -> probs
__device__ int   g_ccol[(size_t)NROWS*CAP];// candidate columns
__device__ __nv_bfloat16 g_urb[PH*PS*PR];  // bf16 copies for TC prepass
__device__ __nv_bfloat16 g_vrb[PH*PS*PR];

// ---------------- zero scratch (counts + o2 accumulator) ---------------------
__global__ void zero_scratch() {
    int i = blockIdx.x * blockDim.x + threadIdx.x;
    if (i < NROWS) g_cnt[i] = 0;
    if (i < PH*PS*PR) g_o2[i] = 0.f;
}

// ---------------- convert ur/vr to bf16 ----------------------------------------
__global__ void cvt_bf16_pair(int n) {
    int i = blockIdx.x * blockDim.x + threadIdx.x;
    if (i < n) {
        g_urb[i] = __float2bfloat16(g_ur[i]);
        g_vrb[i] = __float2bfloat16(g_vr[i]);
    }
}

// ---------------- 768x768 transpose into strided dst ----------------
__global__ void transpose768(const float* __restrict__ src, float* __restrict__ dst,
                             int dstStride, int dstOff) {
    __shared__ float t[32][33];
    int bx = blockIdx.x * 32, by = blockIdx.y * 32;
    int x = bx + threadIdx.x;
    #pragma unroll
    for (int i = 0; i < 32; i += 8) {
        int y = by + threadIdx.y + i;
        t[threadIdx.y + i][threadIdx.x] = src[y * PD + x];
    }
    __syncthreads();
    x = by + threadIdx.x;
    #pragma unroll
    for (int i = 0; i < 32; i += 8) {
        int row = bx + threadIdx.y + i;
        dst[(long long)row * dstStride + dstOff + x] = t[threadIdx.x][threadIdx.y + i];
    }
}

// ---------------- double-buffered NT GEMM (dense projections) ----------------
__global__ __launch_bounds__(256) void gemm_nt(
    const float* __restrict__ A, const float* __restrict__ B,
    const float* __restrict__ B2, int Nsplit,
    float* __restrict__ C,
    int M, int N, int K)
{
    __shared__ float As[2][8][132];
    __shared__ float Bs[2][8][132];

    const int tid = threadIdx.x;
    const int bm = blockIdx.y * 128;
    const int bn = blockIdx.x * 128;

    const float* Bbase; int bnn;
    if (bn < Nsplit) { Bbase = B;  bnn = bn; }
    else             { Bbase = B2; bnn = bn - Nsplit; }

    const int lr = tid >> 1;
    const int lc = (tid & 1) * 4;
    const int tx = tid & 15;
    const int ty = tid >> 4;

    const float* Aptr = A + (long long)(bm + lr) * K + lc;
    const float* Bptr = Bbase + (long long)(bnn + lr) * K + lc;

    float acc[8][8];
    #pragma unroll
    for (int i = 0; i < 8; i++)
        #pragma unroll
        for (int j = 0; j < 8; j++) acc[i][j] = 0.f;

    {
        float4 av = *(const float4*)(Aptr);
        float4 bv = *(const float4*)(Bptr);
        As[0][lc+0][lr] = av.x; As[0][lc+1][lr] = av.y;
        As[0][lc+2][lr] = av.z; As[0][lc+3][lr] = av.w;
        Bs[0][lc+0][lr] = bv.x; Bs[0][lc+1][lr] = bv.y;
        Bs[0][lc+2][lr] = bv.z; Bs[0][lc+3][lr] = bv.w;
    }
    __syncthreads();

    int buf = 0;
    for (int k0 = 8; k0 < K; k0 += 8) {
        float4 av = *(const float4*)(Aptr + k0);
        float4 bv = *(const float4*)(Bptr + k0);
        #pragma unroll
        for (int k = 0; k < 8; k++) {
            float af[8], bf[8];
            *(float4*)&af[0] = *(const float4*)&As[buf][k][ty*4];
            *(float4*)&af[4] = *(const float4*)&As[buf][k][64 + ty*4];
            *(float4*)&bf[0] = *(const float4*)&Bs[buf][k][tx*4];
            *(float4*)&bf[4] = *(const float4*)&Bs[buf][k][64 + tx*4];
            #pragma unroll
            for (int i = 0; i < 8; i++)
                #pragma unroll
                for (int j = 0; j < 8; j++)
                    acc[i][j] = fmaf(af[i], bf[j], acc[i][j]);
        }
        int nb = buf ^ 1;
        As[nb][lc+0][lr] = av.x; As[nb][lc+1][lr] = av.y;
        As[nb][lc+2][lr] = av.z; As[nb][lc+3][lr] = av.w;
        Bs[nb][lc+0][lr] = bv.x; Bs[nb][lc+1][lr] = bv.y;
        Bs[nb][lc+2][lr] = bv.z; Bs[nb][lc+3][lr] = bv.w;
        __syncthreads();
        buf = nb;
    }
    #pragma unroll
    for (int k = 0; k < 8; k++) {
        float af[8], bf[8];
        *(float4*)&af[0] = *(const float4*)&As[buf][k][ty*4];
        *(float4*)&af[4] = *(const float4*)&As[buf][k][64 + ty*4];
        *(float4*)&bf[0] = *(const float4*)&Bs[buf][k][tx*4];
        *(float4*)&bf[4] = *(const float4*)&Bs[buf][k][64 + tx*4];
        #pragma unroll
        for (int i = 0; i < 8; i++)
            #pragma unroll
            for (int j = 0; j < 8; j++)
                acc[i][j] = fmaf(af[i], bf[j], acc[i][j]);
    }

    #pragma unroll
    for (int i = 0; i < 8; i++) {
        int row = bm + ((i < 4) ? (ty*4 + i) : (64 + ty*4 + (i-4)));
        #pragma unroll
        for (int jg = 0; jg < 2; jg++) {
            int col = bn + (jg == 0 ? tx*4 : 64 + tx*4);
            *(float4*)&C[(long long)row * N + col] = *(float4*)&acc[i][jg*4];
        }
    }
}

// ---------------- warp-mma bf16 QK prepass + candidate selection --------------
// Base-target tensor cores: mma.sync.aligned.m16n8k16 (works on plain sm_103).
// Per CTA: 128 q-rows x 128 k-cols of one head; 8 warps in 2(M) x 4(N) grid;
// warp tile 64x32 = 4 m-frags x 4 n-frags; K = 96 = 6 chunks of 16.
#define LDT 104   // bf16 elems per smem row (52 words; stride % 32 = 20 -> conflict-free)
#define QK_SMEM_BYTES (2 * 128 * LDT * 2)

__device__ __forceinline__ void mma16816(float* c, const uint32_t* a, const uint32_t* b) {
    asm volatile(
        "mma.sync.aligned.m16n8k16.row.col.f32.bf16.bf16.f32 "
        "{%0,%1,%2,%3}, {%4,%5,%6,%7}, {%8,%9}, {%0,%1,%2,%3};"
        : "+f"(c[0]), "+f"(c[1]), "+f"(c[2]), "+f"(c[3])
        : "r"(a[0]), "r"(a[1]), "r"(a[2]), "r"(a[3]), "r"(b[0]), "r"(b[1]));
}

__global__ __launch_bounds__(256) void qk_select_mma() {
    extern __shared__ __align__(16) __nv_bfloat16 smem[];
    __nv_bfloat16* As = smem;              // [128][LDT]
    __nv_bfloat16* Bs = smem + 128 * LDT;  // [128][LDT]
    __shared__ float wmax[128][4];

    const int h  = blockIdx.z;
    const int bm = blockIdx.y * 128;
    const int bn = blockIdx.x * 128;
    const int tid = threadIdx.x, lane = tid & 31, w = tid >> 5;
    const int wy = w >> 2, wx = w & 3;

    // load tiles: 128 rows x 96 bf16 each (12 x uint4 per row)
    {
        const uint4* ga = (const uint4*)(g_urb + ((size_t)h*PS + bm) * PR);
        const uint4* gb = (const uint4*)(g_vrb + ((size_t)h*PS + bn) * PR);
        #pragma unroll
        for (int i = 0; i < 6; i++) {
            int idx = tid + i * 256;          // 0..1535
            int row = idx / 12, c = idx % 12;
            *(uint4*)&As[row * LDT + c * 8] = ga[row * 12 + c];
            *(uint4*)&Bs[row * LDT + c * 8] = gb[row * 12 + c];
        }
    }
    __syncthreads();

    float acc[4][4][4];
    #pragma unroll
    for (int mi = 0; mi < 4; mi++)
        #pragma unroll
        for (int ni = 0; ni < 4; ni++)
            #pragma unroll
            for (int c = 0; c < 4; c++) acc[mi][ni][c] = 0.f;

    const int rq = lane >> 2;          // 0..7
    const int q2 = (lane & 3) * 2;     // 0,2,4,6

    #pragma unroll
    for (int kc = 0; kc < 6; kc++) {
        const int k0 = kc * 16;
        uint32_t a[4][4], b[4][2];
        #pragma unroll
        for (int mi = 0; mi < 4; mi++) {
            int r0 = wy*64 + mi*16 + rq;
            a[mi][0] = *(const uint32_t*)&As[(r0    ) * LDT + k0     + q2];
            a[mi][1] = *(const uint32_t*)&As[(r0 + 8) * LDT + k0     + q2];
            a[mi][2] = *(const uint32_t*)&As[(r0    ) * LDT + k0 + 8 + q2];
            a[mi][3] = *(const uint32_t*)&As[(r0 + 8) * LDT + k0 + 8 + q2];
        }
        #pragma unroll
        for (int ni = 0; ni < 4; ni++) {
            int c0 = wx*32 + ni*8 + rq;
            b[ni][0] = *(const uint32_t*)&Bs[c0 * LDT + k0     + q2];
            b[ni][1] = *(const uint32_t*)&Bs[c0 * LDT + k0 + 8 + q2];
        }
        #pragma unroll
        for (int mi = 0; mi < 4; mi++)
            #pragma unroll
            for (int ni = 0; ni < 4; ni++)
                mma16816(acc[mi][ni], a[mi], b[ni]);
    }

    // per-row max across the CTA's 128 columns
    #pragma unroll
    for (int mi = 0; mi < 4; mi++) {
        float m0 = -INFINITY, m1 = -INFINITY;
        #pragma unroll
        for (int ni = 0; ni < 4; ni++) {
            m0 = fmaxf(m0, fmaxf(acc[mi][ni][0], acc[mi][ni][1]));
            m1 = fmaxf(m1, fmaxf(acc[mi][ni][2], acc[mi][ni][3]));
        }
        // lanes sharing a row differ only in (lane&3)
        m0 = fmaxf(m0, __shfl_xor_sync(0xffffffffu, m0, 1));
        m0 = fmaxf(m0, __shfl_xor_sync(0xffffffffu, m0, 2));
        m1 = fmaxf(m1, __shfl_xor_sync(0xffffffffu, m1, 1));
        m1 = fmaxf(m1, __shfl_xor_sync(0xffffffffu, m1, 2));
        if ((lane & 3) == 0) {
            wmax[wy*64 + mi*16 + rq    ][wx] = m0;
            wmax[wy*64 + mi*16 + rq + 8][wx] = m1;
        }
    }
    __syncthreads();

    // threshold + append (unscaled margin 24; required ~14 from bf16 error model)
    #pragma unroll
    for (int mi = 0; mi < 4; mi++) {
        #pragma unroll
        for (int half = 0; half < 2; half++) {
            int row = wy*64 + mi*16 + rq + half*8;
            float rm = fmaxf(fmaxf(wmax[row][0], wmax[row][1]),
                             fmaxf(wmax[row][2], wmax[row][3]));
            float thr = rm - 24.0f;
            long long rid = (long long)h * PS + bm + row;
            #pragma unroll
            for (int ni = 0; ni < 4; ni++) {
                #pragma unroll
                for (int j = 0; j < 2; j++) {
                    float v = acc[mi][ni][half*2 + j];
                    if (v >= thr) {
                        int pos = atomicAdd(&g_cnt[rid], 1);
                        if (pos < CAP)
                            g_ccol[rid*CAP + pos] = bn + wx*32 + ni*8 + q2 + j;
                    }
                }
            }
        }
    }
}

// ---------------- exact fp32 refinement of candidate logits -------------------
__global__ __launch_bounds__(256) void refine_rows(
    const float* __restrict__ urp, const float* __restrict__ vrp)
{
    int w = (blockIdx.x * blockDim.x + threadIdx.x) >> 5;  // one warp per row
    if (w >= NROWS) return;
    int lane = threadIdx.x & 31;
    int h = w >> 11;

    const float* urow = urp + (size_t)w * PR;
    float u0 = urow[lane], u1 = urow[lane + 32], u2 = urow[lane + 64];

    int cnt = g_cnt[w]; if (cnt > CAP) cnt = CAP;
    long long base = (long long)w * CAP;
    const float* vh = vrp + (size_t)h * PS * PR;

    for (int e = 0; e < cnt; e++) {
        int col = g_ccol[base + e];
        const float* vrow = vh + (size_t)col * PR;
        float d = u0 * vrow[lane];
        d = fmaf(u1, vrow[lane + 32], d);
        d = fmaf(u2, vrow[lane + 64], d);
        #pragma unroll
        for (int o = 16; o > 0; o >>= 1) d += __shfl_xor_sync(0xffffffffu, d, o);
        if (lane == 0) g_cval[base + e] = d * (float)PD;
    }
    if (lane == 0) g_cnt[w] = cnt;
}

// ---------------- finalize: per-row softmax over candidates, compact ---------
__global__ void finalize_rows() {
    int row = blockIdx.x * blockDim.x + threadIdx.x;
    if (row >= NROWS) return;
    int cnt = g_cnt[row]; if (cnt > CAP) cnt = CAP;
    long long base = (long long)row * CAP;

    float gmax = -INFINITY;
    for (int i = 0; i < cnt; i++) gmax = fmaxf(gmax, g_cval[base + i]);
    float sum = 0.f;
    for (int i = 0; i < cnt; i++) sum += expf(g_cval[base + i] - gmax);
    float inv = 1.f / sum;
    int out = 0;
    for (int i = 0; i < cnt; i++) {
        float p = expf(g_cval[base + i] - gmax) * inv;
        if (p > 1e-12f) {
            g_cval[base + out] = p;
            g_ccol[base + out] = g_ccol[base + i];
            out++;
        }
    }
    g_cnt[row] = out;
}

// ---------------- sparse PV: o1 gather, o2 scatter ----------------------------
__global__ __launch_bounds__(96) void sparse_pv(
    const float* __restrict__ vrp, const float* __restrict__ uop)
{
    int row = blockIdx.x;             // h*PS + q
    int h = row >> 11;
    int r = threadIdx.x;              // 0..95
    long long base = (long long)row * CAP;
    int cnt = g_cnt[row];

    const float* vrh = vrp + (size_t)h * PS * PR;
    float myuo = uop[(size_t)row * PR + r];

    float acc = 0.f;
    for (int e = 0; e < cnt; e++) {
        float p = g_cval[base + e];
        int col = g_ccol[base + e];
        acc = fmaf(p, vrh[(size_t)col * PR + r], acc);
        atomicAdd(&g_o2[((size_t)h * PS + col) * PR + r], p * myuo);
    }
    g_o1[(size_t)row * PR + r] = acc;
}

// ---------------- RoPE forward: g_uv -> ur, uo, vr ([H,S,R]) -----------------
__global__ void rope_fwd(const float* __restrict__ cosp, const float* __restrict__ sinp) {
    int idx = blockIdx.x * blockDim.x + threadIdx.x;
    if (idx >= PH*PS*PR) return;
    int r = idx % PR;
    int s = (idx / PR) % PS;
    int h = idx / (PR*PS);
    int b = h >> 3, c = h & 7;

    long long base = ((long long)(b*PS + s)) * PD2 + c*PR;
    int   r2  = (r < PR/2) ? r + PR/2 : r - PR/2;
    float sgn = (r < PR/2) ? -1.f : 1.f;

    float xu  = g_uv[base + r];
    float xur = sgn * g_uv[base + r2];
    float xv  = g_uv[base + PD + r];
    float xvr = sgn * g_uv[base + PD + r2];

    long long ci = ((long long)(b*PS + s)) * PR + r;
    float cs = cosp[ci], sn = sinp[ci];

    g_ur[idx] = xu*cs + xur*sn;
    g_uo[idx] = xu*cs - xur*sn;
    g_vr[idx] = xv*cs + xvr*sn;
}

// ---------------- un-RoPE + reassemble to [M, 1536] --------------------------
__global__ void rope_bwd(const float* __restrict__ cosp, const float* __restrict__ sinp) {
    int idx = blockIdx.x * blockDim.x + threadIdx.x;
    if (idx >= PH*PS*PR) return;
    int r = idx % PR;
    int s = (idx / PR) % PS;
    int h = idx / (PR*PS);
    int b = h >> 3, c = h & 7;

    int   r2  = (r < PR/2) ? r + PR/2 : r - PR/2;
    float sgn = (r < PR/2) ? -1.f : 1.f;
    int idx2 = idx - r + r2;

    long long ci = ((long long)(b*PS + s)) * PR + r;
    float cs = cosp[ci], sn = sinp[ci];

    float o1  = g_o1[idx],  o1r = sgn * g_o1[idx2];
    float o2  = g_o2[idx],  o2r = sgn * g_o2[idx2];

    long long dst = ((long long)(b*PS + s)) * PD2 + c*PR + r;
    g_g12[dst]      = o1*cs - o1r*sn;   // rope_o
    g_g12[dst + PD] = o2*cs + o2r*sn;   // rope
}

// ---------------- launch ------------------------------------------------------
extern "C" void kernel_launch(void* const* d_in, const int* in_sizes, int n_in,
                              void* d_out, int out_size) {
    const float* qz  = (const float*)d_in[0];
    const float* cs  = (const float*)d_in[1];
    const float* sn  = (const float*)d_in[2];
    const float* U   = (const float*)d_in[3];
    const float* V   = (const float*)d_in[4];
    float* out = (float*)d_out;

    float *puv, *pur, *puo, *pvr, *po1, *po2, *pg12, *pWt;
    cudaGetSymbolAddress((void**)&puv,  g_uv);
    cudaGetSymbolAddress((void**)&pur,  g_ur);
    cudaGetSymbolAddress((void**)&puo,  g_uo);
    cudaGetSymbolAddress((void**)&pvr,  g_vr);
    cudaGetSymbolAddress((void**)&po1,  g_o1);
    cudaGetSymbolAddress((void**)&po2,  g_o2);
    cudaGetSymbolAddress((void**)&pg12, g_g12);
    cudaGetSymbolAddress((void**)&pWt,  g_Wt);

    cudaFuncSetAttribute(qk_select_mma, cudaFuncAttributeMaxDynamicSharedMemorySize,
                         QK_SMEM_BYTES);

    // zero candidate counts + o2 accumulator
    zero_scratch<<<(PH*PS*PR + 255)/256, 256>>>();

    // build [U^T | V^T] with row stride 1536
    dim3 tb(32, 8), tg(PD/32, PD/32);
    transpose768<<<tg, tb>>>(U, pWt, PD2, 0);
    transpose768<<<tg, tb>>>(V, pWt, PD2, PD);

    // fused input GEMM: g_uv = qz @ [U^T | V^T]
    gemm_nt<<<dim3(PD2/128, PM/128, 1), 256>>>(qz, U, V, PD, puv, PM, PD2, PD);

    // RoPE
    rope_fwd<<<(PH*PS*PR + 255)/256, 256>>>(cs, sn);

    // bf16 copies for the tensor-core prepass
    cvt_bf16_pair<<<(PH*PS*PR + 255)/256, 256>>>(PH*PS*PR);

    // warp-mma bf16 QK prepass + candidate selection
    qk_select_mma<<<dim3(PS/128, PS/128, PH), 256, QK_SMEM_BYTES>>>();

    // exact fp32 logits for candidates
    refine_rows<<<(NROWS*32 + 255)/256, 256>>>(pur, pvr);

    // per-row softmax over candidates
    finalize_rows<<<(NROWS + 127)/128, 128>>>();

    // sparse PV: o1 gather + o2 scatter
    sparse_pv<<<NROWS, 96>>>(pvr, puo);

    // un-RoPE + reassemble into [g1 | g2]
    rope_bwd<<<(PH*PS*PR + 255)/256, 256>>>(cs, sn);

    // fused output GEMM: out = [g1 | g2] @ [Wt rows]  (K = 1536)
    gemm_nt<<<dim3(PD/128, PM/128, 1), 256>>>(pg12, pWt, pWt, 1 << 30, out, PM, PD, PD2);
}

// round 6
// speedup vs baseline: 2.7994x; 1.1669x over previous
#include <cuda_runtime.h>
#include <cuda_bf16.h>
#include <math.h>
#include <stdint.h>

// Problem constants
#define PB 2
#define PS 2048
#define PD 768
#define PC 8
#define PR 96
#define PH 16            // B*C
#define PM (PB*PS)       // 4096
#define PD2 (2*PD)       // 1536
#define K3  (3*PD2)      // 4608: split-K concat for output GEMM
#define CAP 128          // max candidates per row
#define NROWS (PH*PS)    // 32768 attention rows

// ---------------- scratch (device globals) ----------------
__device__ float g_uv [(size_t)PM*PD2];    // [qz@U^T | qz@V^T]   [M,1536]
__device__ float g_ur [PH*PS*PR];          // rope(qz_u)   [H,S,R]
__device__ float g_uo [PH*PS*PR];          // rope_o(qz_u)
__device__ float g_vr [PH*PS*PR];          // rope(qz_v)
__device__ float g_o1 [PH*PS*PR];          // P   @ vr
__device__ float g_o2 [PH*PS*PR];          // P^T @ uo
__device__ int   g_cnt [NROWS];            // candidate counts
__device__ float g_cval[(size_t)NROWS*CAP];// exact candidate logits -> probs
__device__ int   g_ccol[(size_t)NROWS*CAP];// candidate columns
__device__ __nv_bfloat16 g_urb[PH*PS*PR];  // bf16 copies for TC prepass
__device__ __nv_bfloat16 g_vrb[PH*PS*PR];
__device__ __nv_bfloat16 g_a3[(size_t)PM*K3]; // [Ah | Ah | Al] of [g1|g2]
__device__ __nv_bfloat16 g_b3[(size_t)PD*K3]; // [Bh | Bl | Bh] of [U^T|V^T] rows

// ---------------- zero scratch (counts + o2 accumulator) ---------------------
__global__ void zero_scratch() {
    int i = blockIdx.x * blockDim.x + threadIdx.x;
    if (i < NROWS) g_cnt[i] = 0;
    if (i < PH*PS*PR) g_o2[i] = 0.f;
}

// ---------------- 768x768 transpose -> bf16 split-K rows of g_b3 -------------
// src U (dstOff=0) or V (dstOff=PD): B'[n][k]=hi, B'[n][1536+k]=lo, B'[n][3072+k]=hi
__global__ void transpose_split(const float* __restrict__ src, int dstOff) {
    __shared__ float t[32][33];
    int bx = blockIdx.x * 32, by = blockIdx.y * 32;
    int x = bx + threadIdx.x;
    #pragma unroll
    for (int i = 0; i < 32; i += 8) {
        int y = by + threadIdx.y + i;
        t[threadIdx.y + i][threadIdx.x] = src[y * PD + x];
    }
    __syncthreads();
    x = by + threadIdx.x;
    #pragma unroll
    for (int i = 0; i < 32; i += 8) {
        int n = bx + threadIdx.y + i;       // output row (0..767)
        int k = dstOff + x;                 // output col (0..1535)
        float w = t[threadIdx.x][threadIdx.y + i];
        __nv_bfloat16 h = __float2bfloat16(w);
        __nv_bfloat16 l = __float2bfloat16(w - __bfloat162float(h));
        size_t base = (size_t)n * K3;
        g_b3[base + k]          = h;
        g_b3[base + PD2 + k]    = l;
        g_b3[base + 2*PD2 + k]  = h;
    }
}

// ---------------- double-buffered fp32 NT GEMM (input projections) -----------
__global__ __launch_bounds__(256) void gemm_nt(
    const float* __restrict__ A, const float* __restrict__ B,
    const float* __restrict__ B2, int Nsplit,
    float* __restrict__ C,
    int M, int N, int K)
{
    __shared__ float As[2][8][132];
    __shared__ float Bs[2][8][132];

    const int tid = threadIdx.x;
    const int bm = blockIdx.y * 128;
    const int bn = blockIdx.x * 128;

    const float* Bbase; int bnn;
    if (bn < Nsplit) { Bbase = B;  bnn = bn; }
    else             { Bbase = B2; bnn = bn - Nsplit; }

    const int lr = tid >> 1;
    const int lc = (tid & 1) * 4;
    const int tx = tid & 15;
    const int ty = tid >> 4;

    const float* Aptr = A + (long long)(bm + lr) * K + lc;
    const float* Bptr = Bbase + (long long)(bnn + lr) * K + lc;

    float acc[8][8];
    #pragma unroll
    for (int i = 0; i < 8; i++)
        #pragma unroll
        for (int j = 0; j < 8; j++) acc[i][j] = 0.f;

    {
        float4 av = *(const float4*)(Aptr);
        float4 bv = *(const float4*)(Bptr);
        As[0][lc+0][lr] = av.x; As[0][lc+1][lr] = av.y;
        As[0][lc+2][lr] = av.z; As[0][lc+3][lr] = av.w;
        Bs[0][lc+0][lr] = bv.x; Bs[0][lc+1][lr] = bv.y;
        Bs[0][lc+2][lr] = bv.z; Bs[0][lc+3][lr] = bv.w;
    }
    __syncthreads();

    int buf = 0;
    for (int k0 = 8; k0 < K; k0 += 8) {
        float4 av = *(const float4*)(Aptr + k0);
        float4 bv = *(const float4*)(Bptr + k0);
        #pragma unroll
        for (int k = 0; k < 8; k++) {
            float af[8], bf[8];
            *(float4*)&af[0] = *(const float4*)&As[buf][k][ty*4];
            *(float4*)&af[4] = *(const float4*)&As[buf][k][64 + ty*4];
            *(float4*)&bf[0] = *(const float4*)&Bs[buf][k][tx*4];
            *(float4*)&bf[4] = *(const float4*)&Bs[buf][k][64 + tx*4];
            #pragma unroll
            for (int i = 0; i < 8; i++)
                #pragma unroll
                for (int j = 0; j < 8; j++)
                    acc[i][j] = fmaf(af[i], bf[j], acc[i][j]);
        }
        int nb = buf ^ 1;
        As[nb][lc+0][lr] = av.x; As[nb][lc+1][lr] = av.y;
        As[nb][lc+2][lr] = av.z; As[nb][lc+3][lr] = av.w;
        Bs[nb][lc+0][lr] = bv.x; Bs[nb][lc+1][lr] = bv.y;
        Bs[nb][lc+2][lr] = bv.z; Bs[nb][lc+3][lr] = bv.w;
        __syncthreads();
        buf = nb;
    }
    #pragma unroll
    for (int k = 0; k < 8; k++) {
        float af[8], bf[8];
        *(float4*)&af[0] = *(const float4*)&As[buf][k][ty*4];
        *(float4*)&af[4] = *(const float4*)&As[buf][k][64 + ty*4];
        *(float4*)&bf[0] = *(const float4*)&Bs[buf][k][tx*4];
        *(float4*)&bf[4] = *(const float4*)&Bs[buf][k][64 + tx*4];
        #pragma unroll
        for (int i = 0; i < 8; i++)
            #pragma unroll
            for (int j = 0; j < 8; j++)
                acc[i][j] = fmaf(af[i], bf[j], acc[i][j]);
    }

    #pragma unroll
    for (int i = 0; i < 8; i++) {
        int row = bm + ((i < 4) ? (ty*4 + i) : (64 + ty*4 + (i-4)));
        #pragma unroll
        for (int jg = 0; jg < 2; jg++) {
            int col = bn + (jg == 0 ? tx*4 : 64 + tx*4);
            *(float4*)&C[(long long)row * N + col] = *(float4*)&acc[i][jg*4];
        }
    }
}

// ---------------- mma helper ---------------------------------------------------
__device__ __forceinline__ void mma16816(float* c, const uint32_t* a, const uint32_t* b) {
    asm volatile(
        "mma.sync.aligned.m16n8k16.row.col.f32.bf16.bf16.f32 "
        "{%0,%1,%2,%3}, {%4,%5,%6,%7}, {%8,%9}, {%0,%1,%2,%3};"
        : "+f"(c[0]), "+f"(c[1]), "+f"(c[2]), "+f"(c[3])
        : "r"(a[0]), "r"(a[1]), "r"(a[2]), "r"(a[3]), "r"(b[0]), "r"(b[1]));
}

// ---------------- warp-mma bf16 QK prepass + candidate selection --------------
#define LDT 104   // bf16 elems per smem row
#define QK_SMEM_BYTES (2 * 128 * LDT * 2)

__global__ __launch_bounds__(256) void qk_select_mma() {
    extern __shared__ __align__(16) __nv_bfloat16 smem[];
    __nv_bfloat16* As = smem;              // [128][LDT]
    __nv_bfloat16* Bs = smem + 128 * LDT;  // [128][LDT]
    __shared__ float wmax[128][4];

    const int h  = blockIdx.z;
    const int bm = blockIdx.y * 128;
    const int bn = blockIdx.x * 128;
    const int tid = threadIdx.x, lane = tid & 31, w = tid >> 5;
    const int wy = w >> 2, wx = w & 3;

    {
        const uint4* ga = (const uint4*)(g_urb + ((size_t)h*PS + bm) * PR);
        const uint4* gb = (const uint4*)(g_vrb + ((size_t)h*PS + bn) * PR);
        #pragma unroll
        for (int i = 0; i < 6; i++) {
            int idx = tid + i * 256;          // 0..1535
            int row = idx / 12, c = idx % 12;
            *(uint4*)&As[row * LDT + c * 8] = ga[row * 12 + c];
            *(uint4*)&Bs[row * LDT + c * 8] = gb[row * 12 + c];
        }
    }
    __syncthreads();

    float acc[4][4][4];
    #pragma unroll
    for (int mi = 0; mi < 4; mi++)
        #pragma unroll
        for (int ni = 0; ni < 4; ni++)
            #pragma unroll
            for (int c = 0; c < 4; c++) acc[mi][ni][c] = 0.f;

    const int rq = lane >> 2;
    const int q2 = (lane & 3) * 2;

    #pragma unroll
    for (int kc = 0; kc < 6; kc++) {
        const int k0 = kc * 16;
        uint32_t a[4][4], b[4][2];
        #pragma unroll
        for (int mi = 0; mi < 4; mi++) {
            int r0 = wy*64 + mi*16 + rq;
            a[mi][0] = *(const uint32_t*)&As[(r0    ) * LDT + k0     + q2];
            a[mi][1] = *(const uint32_t*)&As[(r0 + 8) * LDT + k0     + q2];
            a[mi][2] = *(const uint32_t*)&As[(r0    ) * LDT + k0 + 8 + q2];
            a[mi][3] = *(const uint32_t*)&As[(r0 + 8) * LDT + k0 + 8 + q2];
        }
        #pragma unroll
        for (int ni = 0; ni < 4; ni++) {
            int c0 = wx*32 + ni*8 + rq;
            b[ni][0] = *(const uint32_t*)&Bs[c0 * LDT + k0     + q2];
            b[ni][1] = *(const uint32_t*)&Bs[c0 * LDT + k0 + 8 + q2];
        }
        #pragma unroll
        for (int mi = 0; mi < 4; mi++)
            #pragma unroll
            for (int ni = 0; ni < 4; ni++)
                mma16816(acc[mi][ni], a[mi], b[ni]);
    }

    #pragma unroll
    for (int mi = 0; mi < 4; mi++) {
        float m0 = -INFINITY, m1 = -INFINITY;
        #pragma unroll
        for (int ni = 0; ni < 4; ni++) {
            m0 = fmaxf(m0, fmaxf(acc[mi][ni][0], acc[mi][ni][1]));
            m1 = fmaxf(m1, fmaxf(acc[mi][ni][2], acc[mi][ni][3]));
        }
        m0 = fmaxf(m0, __shfl_xor_sync(0xffffffffu, m0, 1));
        m0 = fmaxf(m0, __shfl_xor_sync(0xffffffffu, m0, 2));
        m1 = fmaxf(m1, __shfl_xor_sync(0xffffffffu, m1, 1));
        m1 = fmaxf(m1, __shfl_xor_sync(0xffffffffu, m1, 2));
        if ((lane & 3) == 0) {
            wmax[wy*64 + mi*16 + rq    ][wx] = m0;
            wmax[wy*64 + mi*16 + rq + 8][wx] = m1;
        }
    }
    __syncthreads();

    #pragma unroll
    for (int mi = 0; mi < 4; mi++) {
        #pragma unroll
        for (int half = 0; half < 2; half++) {
            int row = wy*64 + mi*16 + rq + half*8;
            float rm = fmaxf(fmaxf(wmax[row][0], wmax[row][1]),
                             fmaxf(wmax[row][2], wmax[row][3]));
            float thr = rm - 20.0f;
            long long rid = (long long)h * PS + bm + row;
            #pragma unroll
            for (int ni = 0; ni < 4; ni++) {
                #pragma unroll
                for (int j = 0; j < 2; j++) {
                    float v = acc[mi][ni][half*2 + j];
                    if (v >= thr) {
                        int pos = atomicAdd(&g_cnt[rid], 1);
                        if (pos < CAP)
                            g_ccol[rid*CAP + pos] = bn + wx*32 + ni*8 + q2 + j;
                    }
                }
            }
        }
    }
}

// ---------------- bf16 split-K output GEMM: out = A'(g12) @ B'(Wt)^T ----------
// A' [PM][K3] bf16, B' [PD][K3] bf16, C [PM][PD] fp32.
#define OK_LD 40
#define OUT_SMEM_BYTES (2 * 2 * 128 * OK_LD * 2)

__global__ __launch_bounds__(256) void tc_gemm_out(float* __restrict__ C) {
    extern __shared__ __align__(16) __nv_bfloat16 dsm[];
    __nv_bfloat16* As = dsm;                       // [2][128*OK_LD]
    __nv_bfloat16* Bs = dsm + 2 * 128 * OK_LD;

    const int bm = blockIdx.y * 128;
    const int bn = blockIdx.x * 128;
    const int tid = threadIdx.x, lane = tid & 31, w = tid >> 5;
    const int wy = w >> 2, wx = w & 3;
    const int rq = lane >> 2, q2 = (lane & 3) * 2;

    // loader indices: 512 uint4 per 128x32 tile; 2 per thread
    const int lrow0 = (tid + 0)   >> 2, lc0 = ((tid + 0)   & 3) * 8;
    const int lrow1 = (tid + 256) >> 2, lc1 = ((tid + 256) & 3) * 8;

    const __nv_bfloat16* Ag = g_a3 + (size_t)bm * K3;
    const __nv_bfloat16* Bg = g_b3 + (size_t)bn * K3;

    float acc[4][4][4];
    #pragma unroll
    for (int mi = 0; mi < 4; mi++)
        #pragma unroll
        for (int ni = 0; ni < 4; ni++)
            #pragma unroll
            for (int c = 0; c < 4; c++) acc[mi][ni][c] = 0.f;

    // prologue: chunk 0
    {
        *(uint4*)&As[lrow0*OK_LD + lc0] = *(const uint4*)&Ag[(size_t)lrow0*K3 + lc0];
        *(uint4*)&As[lrow1*OK_LD + lc1] = *(const uint4*)&Ag[(size_t)lrow1*K3 + lc1];
        *(uint4*)&Bs[lrow0*OK_LD + lc0] = *(const uint4*)&Bg[(size_t)lrow0*K3 + lc0];
        *(uint4*)&Bs[lrow1*OK_LD + lc1] = *(const uint4*)&Bg[(size_t)lrow1*K3 + lc1];
    }
    __syncthreads();

    int buf = 0;
    for (int k0 = 32; k0 <= K3; k0 += 32) {
        uint4 pa0, pa1, pb0, pb1;
        bool more = (k0 < K3);
        if (more) {
            pa0 = *(const uint4*)&Ag[(size_t)lrow0*K3 + k0 + lc0];
            pa1 = *(const uint4*)&Ag[(size_t)lrow1*K3 + k0 + lc1];
            pb0 = *(const uint4*)&Bg[(size_t)lrow0*K3 + k0 + lc0];
            pb1 = *(const uint4*)&Bg[(size_t)lrow1*K3 + k0 + lc1];
        }
        const __nv_bfloat16* Ab = As + buf * 128 * OK_LD;
        const __nv_bfloat16* Bb = Bs + buf * 128 * OK_LD;
        #pragma unroll
        for (int kk = 0; kk < 32; kk += 16) {
            uint32_t a[4][4], b[4][2];
            #pragma unroll
            for (int mi = 0; mi < 4; mi++) {
                int r0 = wy*64 + mi*16 + rq;
                a[mi][0] = *(const uint32_t*)&Ab[(r0    ) * OK_LD + kk     + q2];
                a[mi][1] = *(const uint32_t*)&Ab[(r0 + 8) * OK_LD + kk     + q2];
                a[mi][2] = *(const uint32_t*)&Ab[(r0    ) * OK_LD + kk + 8 + q2];
                a[mi][3] = *(const uint32_t*)&Ab[(r0 + 8) * OK_LD + kk + 8 + q2];
            }
            #pragma unroll
            for (int ni = 0; ni < 4; ni++) {
                int c0 = wx*32 + ni*8 + rq;
                b[ni][0] = *(const uint32_t*)&Bb[c0 * OK_LD + kk     + q2];
                b[ni][1] = *(const uint32_t*)&Bb[c0 * OK_LD + kk + 8 + q2];
            }
            #pragma unroll
            for (int mi = 0; mi < 4; mi++)
                #pragma unroll
                for (int ni = 0; ni < 4; ni++)
                    mma16816(acc[mi][ni], a[mi], b[ni]);
        }
        if (more) {
            int nb = buf ^ 1;
            __nv_bfloat16* An = As + nb * 128 * OK_LD;
            __nv_bfloat16* Bn = Bs + nb * 128 * OK_LD;
            *(uint4*)&An[lrow0*OK_LD + lc0] = pa0;
            *(uint4*)&An[lrow1*OK_LD + lc1] = pa1;
            *(uint4*)&Bn[lrow0*OK_LD + lc0] = pb0;
            *(uint4*)&Bn[lrow1*OK_LD + lc1] = pb1;
            __syncthreads();
            buf = nb;
        }
    }

    // epilogue
    #pragma unroll
    for (int mi = 0; mi < 4; mi++) {
        #pragma unroll
        for (int ni = 0; ni < 4; ni++) {
            int r0 = bm + wy*64 + mi*16 + rq;
            int c0 = bn + wx*32 + ni*8 + q2;
            *(float2*)&C[(size_t)r0 * PD + c0]       = make_float2(acc[mi][ni][0], acc[mi][ni][1]);
            *(float2*)&C[(size_t)(r0 + 8) * PD + c0] = make_float2(acc[mi][ni][2], acc[mi][ni][3]);
        }
    }
}

// ---------------- exact fp32 refinement of candidate logits -------------------
__global__ __launch_bounds__(256) void refine_rows(
    const float* __restrict__ urp, const float* __restrict__ vrp)
{
    int w = (blockIdx.x * blockDim.x + threadIdx.x) >> 5;  // one warp per row
    if (w >= NROWS) return;
    int lane = threadIdx.x & 31;
    int h = w >> 11;

    const float* urow = urp + (size_t)w * PR;
    float u0 = urow[lane], u1 = urow[lane + 32], u2 = urow[lane + 64];

    int cnt = g_cnt[w]; if (cnt > CAP) cnt = CAP;
    long long base = (long long)w * CAP;
    const float* vh = vrp + (size_t)h * PS * PR;

    for (int e = 0; e < cnt; e++) {
        int col = g_ccol[base + e];
        const float* vrow = vh + (size_t)col * PR;
        float d = u0 * vrow[lane];
        d = fmaf(u1, vrow[lane + 32], d);
        d = fmaf(u2, vrow[lane + 64], d);
        #pragma unroll
        for (int o = 16; o > 0; o >>= 1) d += __shfl_xor_sync(0xffffffffu, d, o);
        if (lane == 0) g_cval[base + e] = d * (float)PD;
    }
    if (lane == 0) g_cnt[w] = cnt;
}

// ---------------- finalize: per-row softmax over candidates, compact ---------
__global__ void finalize_rows() {
    int row = blockIdx.x * blockDim.x + threadIdx.x;
    if (row >= NROWS) return;
    int cnt = g_cnt[row]; if (cnt > CAP) cnt = CAP;
    long long base = (long long)row * CAP;

    float gmax = -INFINITY;
    for (int i = 0; i < cnt; i++) gmax = fmaxf(gmax, g_cval[base + i]);
    float sum = 0.f;
    for (int i = 0; i < cnt; i++) sum += expf(g_cval[base + i] - gmax);
    float inv = 1.f / sum;
    int out = 0;
    for (int i = 0; i < cnt; i++) {
        float p = expf(g_cval[base + i] - gmax) * inv;
        if (p > 1e-12f) {
            g_cval[base + out] = p;
            g_ccol[base + out] = g_ccol[base + i];
            out++;
        }
    }
    g_cnt[row] = out;
}

// ---------------- sparse PV: o1 gather, o2 scatter ----------------------------
__global__ __launch_bounds__(96) void sparse_pv(
    const float* __restrict__ vrp, const float* __restrict__ uop)
{
    int row = blockIdx.x;             // h*PS + q
    int h = row >> 11;
    int r = threadIdx.x;              // 0..95
    long long base = (long long)row * CAP;
    int cnt = g_cnt[row];

    const float* vrh = vrp + (size_t)h * PS * PR;
    float myuo = uop[(size_t)row * PR + r];

    float acc = 0.f;
    for (int e = 0; e < cnt; e++) {
        float p = g_cval[base + e];
        int col = g_ccol[base + e];
        acc = fmaf(p, vrh[(size_t)col * PR + r], acc);
        atomicAdd(&g_o2[((size_t)h * PS + col) * PR + r], p * myuo);
    }
    g_o1[(size_t)row * PR + r] = acc;
}

// ---------------- RoPE forward: g_uv -> ur, uo, vr (+ bf16 copies) ------------
__global__ void rope_fwd(const float* __restrict__ cosp, const float* __restrict__ sinp) {
    int idx = blockIdx.x * blockDim.x + threadIdx.x;
    if (idx >= PH*PS*PR) return;
    int r = idx % PR;
    int s = (idx / PR) % PS;
    int h = idx / (PR*PS);
    int b = h >> 3, c = h & 7;

    long long base = ((long long)(b*PS + s)) * PD2 + c*PR;
    int   r2  = (r < PR/2) ? r + PR/2 : r - PR/2;
    float sgn = (r < PR/2) ? -1.f : 1.f;

    float xu  = g_uv[base + r];
    float xur = sgn * g_uv[base + r2];
    float xv  = g_uv[base + PD + r];
    float xvr = sgn * g_uv[base + PD + r2];

    long long ci = ((long long)(b*PS + s)) * PR + r;
    float cs = cosp[ci], sn = sinp[ci];

    float ur = xu*cs + xur*sn;
    float vr = xv*cs + xvr*sn;
    g_ur[idx] = ur;
    g_uo[idx] = xu*cs - xur*sn;
    g_vr[idx] = vr;
    g_urb[idx] = __float2bfloat16(ur);
    g_vrb[idx] = __float2bfloat16(vr);
}

// ---------------- un-RoPE + emit bf16 split-K rows of g_a3 --------------------
__global__ void rope_bwd(const float* __restrict__ cosp, const float* __restrict__ sinp) {
    int idx = blockIdx.x * blockDim.x + threadIdx.x;
    if (idx >= PH*PS*PR) return;
    int r = idx % PR;
    int s = (idx / PR) % PS;
    int h = idx / (PR*PS);
    int b = h >> 3, c = h & 7;

    int   r2  = (r < PR/2) ? r + PR/2 : r - PR/2;
    float sgn = (r < PR/2) ? -1.f : 1.f;
    int idx2 = idx - r + r2;

    long long ci = ((long long)(b*PS + s)) * PR + r;
    float cs = cosp[ci], sn = sinp[ci];

    float o1  = g_o1[idx],  o1r = sgn * g_o1[idx2];
    float o2  = g_o2[idx],  o2r = sgn * g_o2[idx2];

    float v1 = o1*cs - o1r*sn;   // rope_o -> col k1
    float v2 = o2*cs + o2r*sn;   // rope   -> col k2

    int m = b*PS + s;
    int k1 = c*PR + r;
    int k2 = PD + c*PR + r;
    size_t baseA = (size_t)m * K3;

    __nv_bfloat16 h1 = __float2bfloat16(v1);
    __nv_bfloat16 l1 = __float2bfloat16(v1 - __bfloat162float(h1));
    __nv_bfloat16 h2 = __float2bfloat16(v2);
    __nv_bfloat16 l2 = __float2bfloat16(v2 - __bfloat162float(h2));

    g_a3[baseA + k1]          = h1;
    g_a3[baseA + PD2 + k1]    = h1;
    g_a3[baseA + 2*PD2 + k1]  = l1;
    g_a3[baseA + k2]          = h2;
    g_a3[baseA + PD2 + k2]    = h2;
    g_a3[baseA + 2*PD2 + k2]  = l2;
}

// ---------------- launch ------------------------------------------------------
extern "C" void kernel_launch(void* const* d_in, const int* in_sizes, int n_in,
                              void* d_out, int out_size) {
    const float* qz  = (const float*)d_in[0];
    const float* cs  = (const float*)d_in[1];
    const float* sn  = (const float*)d_in[2];
    const float* U   = (const float*)d_in[3];
    const float* V   = (const float*)d_in[4];
    float* out = (float*)d_out;

    float *puv, *pur, *puo, *pvr, *po1, *po2;
    cudaGetSymbolAddress((void**)&puv,  g_uv);
    cudaGetSymbolAddress((void**)&pur,  g_ur);
    cudaGetSymbolAddress((void**)&puo,  g_uo);
    cudaGetSymbolAddress((void**)&pvr,  g_vr);
    cudaGetSymbolAddress((void**)&po1,  g_o1);
    cudaGetSymbolAddress((void**)&po2,  g_o2);

    cudaFuncSetAttribute(qk_select_mma, cudaFuncAttributeMaxDynamicSharedMemorySize,
                         QK_SMEM_BYTES);
    cudaFuncSetAttribute(tc_gemm_out, cudaFuncAttributeMaxDynamicSharedMemorySize,
                         OUT_SMEM_BYTES);

    // zero candidate counts + o2 accumulator
    zero_scratch<<<(PH*PS*PR + 255)/256, 256>>>();

    // build split-K B' = [U^T|V^T] hi/lo rows
    dim3 tb(32, 8), tg(PD/32, PD/32);
    transpose_split<<<tg, tb>>>(U, 0);
    transpose_split<<<tg, tb>>>(V, PD);

    // fused input GEMM (fp32 exact): g_uv = qz @ [U^T | V^T]
    gemm_nt<<<dim3(PD2/128, PM/128, 1), 256>>>(qz, U, V, PD, puv, PM, PD2, PD);

    // RoPE (+ bf16 copies for the TC prepass)
    rope_fwd<<<(PH*PS*PR + 255)/256, 256>>>(cs, sn);

    // warp-mma bf16 QK prepass + candidate selection
    qk_select_mma<<<dim3(PS/128, PS/128, PH), 256, QK_SMEM_BYTES>>>();

    // exact fp32 logits for candidates
    refine_rows<<<(NROWS*32 + 255)/256, 256>>>(pur, pvr);

    // per-row softmax over candidates
    finalize_rows<<<(NROWS + 127)/128, 128>>>();

    // sparse PV: o1 gather + o2 scatter
    sparse_pv<<<NROWS, 96>>>(pvr, puo);

    // un-RoPE + emit split-K A'
    rope_bwd<<<(PH*PS*PR + 255)/256, 256>>>(cs, sn);

    // bf16 split-K output GEMM: out = A' @ B'^T  (exact to ~4e-6)
    tc_gemm_out<<<dim3(PD/128, PM/128), 256, OUT_SMEM_BYTES>>>(out);
}